// round 9
// baseline (speedup 1.0000x reference)
#include <cuda_runtime.h>
#include <math.h>

// ---------------- problem constants ----------------
#define BB 4
#define CC 21
#define HWP 16384      // 128*128
#define DD 256
#define AA 84          // B*C anchor rows
#define VV 100         // views per anchor
#define NROW 8400      // A*V
#define NPAD 8448      // padded to 66*128
#define POS 400        // positives per row (incl. self)
#define NCB 66         // column blocks of 128
#define BM 128
#define BN 128
#define BKK 16

// ---------------- device scratch (static, no allocs) ----------------
__device__ int   g_pred[BB*HWP];
__device__ int   g_idx[AA*VV];
__device__ float g_cf[(size_t)NPAD*DD];        // gathered normalized features, [n][d]
__device__ float g_P[(size_t)NROW*POS];        // positive logits
__device__ float g_NSpart[(size_t)NROW*NCB];   // per (row, col-block) neg-exp partial sums
__device__ float g_rowval[NROW];

// ---------------- helpers ----------------
__device__ __forceinline__ unsigned long long pk2(float lo, float hi){
    unsigned long long r;
    asm("mov.b64 %0, {%1, %2};" : "=l"(r) : "f"(lo), "f"(hi));
    return r;
}
__device__ __forceinline__ void upk2(unsigned long long v, float& lo, float& hi){
    asm("mov.b64 {%0, %1}, %2;" : "=f"(lo), "=f"(hi) : "l"(v));
}
__device__ __forceinline__ void ffma2(unsigned long long& d, unsigned long long a, unsigned long long b){
    asm("fma.rn.f32x2 %0, %1, %2, %0;" : "+l"(d) : "l"(a), "l"(b));
}
// fast exp on the FMA pipe: exp(x) = 2^(x*log2e), |x| <= ~10.2 here. rel err ~2e-6.
__device__ __forceinline__ float fexp(float x){
    float t  = x * 1.4426950408889634f;
    float fk = t + 12582912.0f;                   // round-to-nearest via 1.5*2^23
    int   ki = __float_as_int(fk) - 0x4B400000;
    float r  = t - (fk - 12582912.0f);            // r in [-0.5, 0.5]
    float p  = 1.3333558146e-3f;
    p = fmaf(p, r, 9.6181291076e-3f);
    p = fmaf(p, r, 5.5504108664e-2f);
    p = fmaf(p, r, 2.4022650696e-1f);
    p = fmaf(p, r, 6.9314718056e-1f);
    p = fmaf(p, r, 1.0f);
    return __int_as_float(__float_as_int(p) + (ki << 23));
}

// ---------------- kernel 1: bilinear upsample (64->128, half-pixel) + argmax over 21 classes ----------------
__global__ void k_pred(const float* __restrict__ predict){
    int tid = blockIdx.x*blockDim.x + threadIdx.x;
    if (tid >= BB*HWP) return;
    int b = tid >> 14;
    int p = tid & (HWP-1);
    int y = p >> 7, x = p & 127;
    float fy = fminf(fmaxf(0.5f*(float)y - 0.25f, 0.0f), 63.0f);
    float fx = fminf(fmaxf(0.5f*(float)x - 0.25f, 0.0f), 63.0f);
    int y0 = (int)fy, x0 = (int)fx;
    float wy = fy - (float)y0, wx = fx - (float)x0;
    int y1 = min(y0+1, 63), x1 = min(x0+1, 63);
    const float* pb = predict + (size_t)b*CC*4096;
    float best = -3.4e38f; int bc = 0;
    #pragma unroll
    for (int c = 0; c < CC; c++){
        const float* pc = pb + c*4096;
        float v00 = pc[y0*64+x0], v01 = pc[y0*64+x1];
        float v10 = pc[y1*64+x0], v11 = pc[y1*64+x1];
        float top = v00 + wx*(v01-v00);
        float bot = v10 + wx*(v11-v10);
        float v = top + wy*(bot-top);
        if (v > best){ best = v; bc = c; }
    }
    g_pred[tid] = bc;
}

// ---------------- kernel 2: per-(b,c) hard/easy selection (deterministic rank-based) ----------------
__global__ void k_select(const int* __restrict__ labels){
    __shared__ int sh_h[256], sh_e[256], sh_ph[256], sh_pe[256];
    __shared__ int s_hk, s_ek, s_S;
    int row = blockIdx.x;
    int b = row / CC, c = row % CC;
    int t = threadIdx.x;
    unsigned long long hbits = 0ull, ebits = 0ull;
    int base = b*HWP + t*64;
    for (int q = 0; q < 64; q++){
        int pr = g_pred[base+q];
        int lb = labels[base+q];
        if (pr == c){ if (lb == c) ebits |= (1ull<<q); else hbits |= (1ull<<q); }
    }
    sh_h[t] = __popcll(hbits); sh_e[t] = __popcll(ebits);
    __syncthreads();
    if (t == 0){
        int rh = 0, re = 0;
        for (int u = 0; u < 256; u++){ sh_ph[u]=rh; sh_pe[u]=re; rh+=sh_h[u]; re+=sh_e[u]; }
        int nh = rh, ne = re;
        int hk;
        if (nh >= 50 && ne >= 50) hk = 50;
        else if (nh >= 50)        hk = 100 - ne;
        else                      hk = nh;
        int ek = 100 - hk;
        s_hk = hk; s_ek = ek;
        s_S = min(nh, hk) + min(ne, ek);
    }
    __syncthreads();
    int hb = sh_ph[t], eb = sh_pe[t];
    int hk = s_hk, ek = s_ek, S = s_S;
    for (int q = 0; q < 64; q++){
        int p = t*64 + q;
        int slot;
        if ((hbits>>q)&1ull){
            if (hb < hk) slot = hb + min(eb, ek);
            else         slot = S + (p - min(hb,hk) - min(eb,ek));
            hb++;
        } else if ((ebits>>q)&1ull){
            if (eb < ek) slot = min(hb, hk) + eb;
            else         slot = S + (p - min(hb,hk) - min(eb,ek));
            eb++;
        } else {
            slot = S + (p - min(hb,hk) - min(eb,ek));
        }
        if (slot < VV) g_idx[row*VV + slot] = p;
    }
}

// ---------------- kernel 3: gather + L2-normalize -> cf[v*84+a][d] ----------------
__global__ void k_gather(const float* __restrict__ feats){
    int gw   = (blockIdx.x*blockDim.x + threadIdx.x) >> 5;
    int lane = threadIdx.x & 31;
    if (gw >= NPAD) return;
    if (gw >= NROW){   // zero the pad rows every call (deterministic)
        #pragma unroll
        for (int q = 0; q < 8; q++) g_cf[(size_t)gw*DD + lane + 32*q] = 0.0f;
        return;
    }
    int a = gw / VV, v = gw % VV;
    int b = a / CC;
    int p = g_idx[gw];
    const float* fb = feats + (size_t)b*DD*HWP + p;
    float vals[8]; float ss = 0.f;
    #pragma unroll
    for (int q = 0; q < 8; q++){
        vals[q] = fb[(size_t)(lane + 32*q)*HWP];
        ss += vals[q]*vals[q];
    }
    #pragma unroll
    for (int m = 16; m > 0; m >>= 1) ss += __shfl_xor_sync(0xffffffffu, ss, m);
    float sc = 1.0f / fmaxf(sqrtf(ss), 1e-12f);
    int n = v*AA + a;
    #pragma unroll
    for (int q = 0; q < 8; q++) g_cf[(size_t)n*DD + lane + 32*q] = vals[q]*sc;
}

// ---------------- kernel 4: fused Gram GEMM (f32x2 FFMA2) + contrastive epilogue ----------------
__global__ __launch_bounds__(256) void k_gemm(){
    __shared__ float As[BKK][BM+4];
    __shared__ float Bs[BKK][BN+4];
    int bi = blockIdx.y, bj = blockIdx.x;
    int i0 = bi*BM, j0 = bj*BN;
    int t  = threadIdx.x;
    int tx = t & 15, ty = t >> 4;

    unsigned long long acc[8][4];
    #pragma unroll
    for (int u = 0; u < 8; u++)
        #pragma unroll
        for (int w = 0; w < 4; w++) acc[u][w] = 0ull;

    for (int kc = 0; kc < DD/BKK; kc++){
        int kk0 = kc*BKK;
        #pragma unroll
        for (int u = 0; u < 2; u++){
            int f  = t + u*256;
            int m  = f >> 2;
            int kq = (f & 3) << 2;
            const float4 va = *(const float4*)&g_cf[(size_t)(i0+m)*DD + kk0 + kq];
            As[kq+0][m]=va.x; As[kq+1][m]=va.y; As[kq+2][m]=va.z; As[kq+3][m]=va.w;
            const float4 vb = *(const float4*)&g_cf[(size_t)(j0+m)*DD + kk0 + kq];
            Bs[kq+0][m]=vb.x; Bs[kq+1][m]=vb.y; Bs[kq+2][m]=vb.z; Bs[kq+3][m]=vb.w;
        }
        __syncthreads();
        #pragma unroll
        for (int k = 0; k < BKK; k++){
            float4 a0 = *(const float4*)&As[k][ty*4];
            float4 a1 = *(const float4*)&As[k][64+ty*4];
            float4 b0 = *(const float4*)&Bs[k][tx*4];
            float4 b1 = *(const float4*)&Bs[k][64+tx*4];
            unsigned long long bp[4];
            bp[0]=pk2(b0.x,b0.y); bp[1]=pk2(b0.z,b0.w);
            bp[2]=pk2(b1.x,b1.y); bp[3]=pk2(b1.z,b1.w);
            float av[8] = {a0.x,a0.y,a0.z,a0.w,a1.x,a1.y,a1.z,a1.w};
            #pragma unroll
            for (int ai = 0; ai < 8; ai++){
                unsigned long long ad = pk2(av[ai], av[ai]);
                #pragma unroll
                for (int w = 0; w < 4; w++) ffma2(acc[ai][w], ad, bp[w]);
            }
        }
        __syncthreads();
    }

    // ---- epilogue: logits = dot*10; positives -> g_P, negatives -> exp-sum partials ----
    int ri[8], cj[8], imod[8], jmod[8], jdiv[8];
    #pragma unroll
    for (int g = 0; g < 8; g++){
        int rg = ty*4 + (g&3) + ((g>>2)<<6);
        int cg = tx*4 + (g&3) + ((g>>2)<<6);
        ri[g] = i0 + rg; cj[g] = j0 + cg;
        imod[g] = ri[g] % CC; jmod[g] = cj[g] % CC; jdiv[g] = cj[g] / CC;
    }
    float rowsum[8];
    #pragma unroll
    for (int g = 0; g < 8; g++) rowsum[g] = 0.f;

    #pragma unroll
    for (int ai = 0; ai < 8; ai++){
        if (ri[ai] >= NROW) continue;
        #pragma unroll
        for (int w = 0; w < 4; w++){
            float lo, hi;
            upk2(acc[ai][w], lo, hi);
            int g0 = 2*w, g1 = 2*w + 1;
            if (cj[g0] < NROW){
                float l = lo * 10.0f;
                if (imod[ai] == jmod[g0]) g_P[(size_t)ri[ai]*POS + jdiv[g0]] = l;
                else                      rowsum[ai] += fexp(l);
            }
            if (cj[g1] < NROW){
                float l = hi * 10.0f;
                if (imod[ai] == jmod[g1]) g_P[(size_t)ri[ai]*POS + jdiv[g1]] = l;
                else                      rowsum[ai] += fexp(l);
            }
        }
    }
    // reduce rowsum across the 16 tx-lanes that share the same rows (same ty)
    #pragma unroll
    for (int m = 8; m > 0; m >>= 1)
        #pragma unroll
        for (int g = 0; g < 8; g++)
            rowsum[g] += __shfl_xor_sync(0xffffffffu, rowsum[g], m);
    if (tx == 0){
        #pragma unroll
        for (int g = 0; g < 8; g++)
            if (ri[g] < NROW) g_NSpart[(size_t)ri[g]*NCB + bj] = rowsum[g];
    }
}

// ---------------- kernel 5: per-row finalize: neg_sum reduce + positive log-prob mean ----------------
__global__ void k_finalize(){
    int gw   = (blockIdx.x*blockDim.x + threadIdx.x) >> 5;
    int lane = threadIdx.x & 31;
    if (gw >= NROW) return;
    float ns = 0.f;
    for (int jb = lane; jb < NCB; jb += 32) ns += g_NSpart[(size_t)gw*NCB + jb];
    #pragma unroll
    for (int m = 16; m > 0; m >>= 1) ns += __shfl_xor_sync(0xffffffffu, ns, m);
    int kself = gw / CC;    // self column index within positives
    float acc = 0.f;
    for (int k = lane; k < POS; k += 32){
        if (k == kself) continue;
        float l = g_P[(size_t)gw*POS + k];
        acc += l - __logf(__expf(l) + ns);
    }
    #pragma unroll
    for (int m = 16; m > 0; m >>= 1) acc += __shfl_xor_sync(0xffffffffu, acc, m);
    if (lane == 0) g_rowval[gw] = acc / 399.0f;
}

// ---------------- kernel 6: deterministic final reduction ----------------
__global__ void k_reduce(float* __restrict__ out){
    __shared__ float sh[256];
    int t = threadIdx.x;
    float s = 0.f;
    for (int i = t; i < NROW; i += 256) s += g_rowval[i];
    sh[t] = s; __syncthreads();
    for (int m = 128; m > 0; m >>= 1){
        if (t < m) sh[t] += sh[t+m];
        __syncthreads();
    }
    if (t == 0) out[0] = -(sh[0] / (float)NROW);
}

// ---------------- launch ----------------
extern "C" void kernel_launch(void* const* d_in, const int* in_sizes, int n_in,
                              void* d_out, int out_size){
    const float* feats   = nullptr;
    const float* predict = nullptr;
    const int*   labels  = nullptr;
    for (int i = 0; i < n_in; i++){
        if      (in_sizes[i] == BB*DD*HWP)   feats   = (const float*)d_in[i];
        else if (in_sizes[i] == BB*CC*4096)  predict = (const float*)d_in[i];
        else if (in_sizes[i] == BB*HWP)      labels  = (const int*)d_in[i];
    }
    k_pred<<<(BB*HWP)/256, 256>>>(predict);
    k_select<<<AA, 256>>>(labels);
    k_gather<<<NPAD/8, 256>>>(feats);
    dim3 g4(NCB, NCB);
    k_gemm<<<g4, 256>>>();
    k_finalize<<<NROW/8, 256>>>();
    k_reduce<<<1, 256>>>((float*)d_out);
}

// round 12
// speedup vs baseline: 2.9875x; 2.9875x over previous
#include <cuda_runtime.h>
#include <cuda_bf16.h>
#include <cstdint>
#include <math.h>

// ---------------- problem constants ----------------
#define BB 4
#define CC 21
#define HWP 16384      // 128*128
#define DD 256
#define AA 84          // B*C anchor rows
#define VV 100         // views per anchor
#define NROW 8400      // A*V
#define NPAD 8448      // padded to 66*128
#define POS 400        // positives per row (incl. self)
#define NCB 66         // column blocks of 128
#define NSW (NCB*2)    // neg-sum partials per row (2 wn-halves per col block)

// ---------------- device scratch (static, no allocs) ----------------
__device__ int   g_pred[BB*HWP];
__device__ int   g_idx[AA*VV];
__device__ __align__(16) __nv_bfloat16 g_cfb[(size_t)NPAD*DD];  // normalized bf16 features [n][d]
__device__ float g_P[(size_t)NROW*POS];        // positive logits
__device__ float g_NSpart[(size_t)NROW*NSW];   // per (row, col-block, wn) neg-exp partials
__device__ float g_rowval[NROW];

// ---------------- helpers ----------------
__device__ __forceinline__ uint32_t smem_u32(const void* p){
    uint32_t a;
    asm("{ .reg .u64 t; cvta.to.shared.u64 t, %1; cvt.u32.u64 %0, t; }" : "=r"(a) : "l"(p));
    return a;
}
__device__ __forceinline__ void ldsm4(uint32_t* r, uint32_t addr){
    asm volatile("ldmatrix.sync.aligned.m8n8.x4.shared.b16 {%0,%1,%2,%3}, [%4];"
        : "=r"(r[0]), "=r"(r[1]), "=r"(r[2]), "=r"(r[3]) : "r"(addr));
}
__device__ __forceinline__ void mma16816(float* d, const uint32_t* a, uint32_t b0, uint32_t b1){
    asm volatile("mma.sync.aligned.m16n8k16.row.col.f32.bf16.bf16.f32 "
        "{%0,%1,%2,%3}, {%4,%5,%6,%7}, {%8,%9}, {%0,%1,%2,%3};"
        : "+f"(d[0]), "+f"(d[1]), "+f"(d[2]), "+f"(d[3])
        : "r"(a[0]), "r"(a[1]), "r"(a[2]), "r"(a[3]), "r"(b0), "r"(b1));
}

// ---------------- kernel 1: bilinear upsample (64->128) + argmax over 21 classes ----------------
__global__ void k_pred(const float* __restrict__ predict){
    int tid = blockIdx.x*blockDim.x + threadIdx.x;
    if (tid >= BB*HWP) return;
    int b = tid >> 14;
    int p = tid & (HWP-1);
    int y = p >> 7, x = p & 127;
    float fy = fminf(fmaxf(0.5f*(float)y - 0.25f, 0.0f), 63.0f);
    float fx = fminf(fmaxf(0.5f*(float)x - 0.25f, 0.0f), 63.0f);
    int y0 = (int)fy, x0 = (int)fx;
    float wy = fy - (float)y0, wx = fx - (float)x0;
    int y1 = min(y0+1, 63), x1 = min(x0+1, 63);
    const float* pb = predict + (size_t)b*CC*4096;
    float best = -3.4e38f; int bc = 0;
    #pragma unroll
    for (int c = 0; c < CC; c++){
        const float* pc = pb + c*4096;
        float v00 = pc[y0*64+x0], v01 = pc[y0*64+x1];
        float v10 = pc[y1*64+x0], v11 = pc[y1*64+x1];
        float top = v00 + wx*(v01-v00);
        float bot = v10 + wx*(v11-v10);
        float v = top + wy*(bot-top);
        if (v > best){ best = v; bc = c; }
    }
    g_pred[tid] = bc;
}

// ---------------- kernel 2: per-(b,c) hard/easy selection (deterministic rank-based) ----------------
__global__ void k_select(const int* __restrict__ labels){
    __shared__ int sh_h[256], sh_e[256], sh_ph[256], sh_pe[256];
    __shared__ int s_hk, s_ek, s_S;
    int row = blockIdx.x;
    int b = row / CC, c = row % CC;
    int t = threadIdx.x;
    unsigned long long hbits = 0ull, ebits = 0ull;
    int base = b*HWP + t*64;
    for (int q = 0; q < 64; q++){
        int pr = g_pred[base+q];
        int lb = labels[base+q];
        if (pr == c){ if (lb == c) ebits |= (1ull<<q); else hbits |= (1ull<<q); }
    }
    sh_h[t] = __popcll(hbits); sh_e[t] = __popcll(ebits);
    __syncthreads();
    if (t == 0){
        int rh = 0, re = 0;
        for (int u = 0; u < 256; u++){ sh_ph[u]=rh; sh_pe[u]=re; rh+=sh_h[u]; re+=sh_e[u]; }
        int nh = rh, ne = re;
        int hk;
        if (nh >= 50 && ne >= 50) hk = 50;
        else if (nh >= 50)        hk = 100 - ne;
        else                      hk = nh;
        int ek = 100 - hk;
        s_hk = hk; s_ek = ek;
        s_S = min(nh, hk) + min(ne, ek);
    }
    __syncthreads();
    int hb = sh_ph[t], eb = sh_pe[t];
    int hk = s_hk, ek = s_ek, S = s_S;
    for (int q = 0; q < 64; q++){
        int p = t*64 + q;
        int slot;
        if ((hbits>>q)&1ull){
            if (hb < hk) slot = hb + min(eb, ek);
            else         slot = S + (p - min(hb,hk) - min(eb,ek));
            hb++;
        } else if ((ebits>>q)&1ull){
            if (eb < ek) slot = min(hb, hk) + eb;
            else         slot = S + (p - min(hb,hk) - min(eb,ek));
            eb++;
        } else {
            slot = S + (p - min(hb,hk) - min(eb,ek));
        }
        if (slot < VV) g_idx[row*VV + slot] = p;
    }
}

// ---------------- kernel 3: gather + L2-normalize -> bf16 cf[v*84+a][d] ----------------
__global__ void k_gather(const float* __restrict__ feats){
    int gw   = (blockIdx.x*blockDim.x + threadIdx.x) >> 5;
    int lane = threadIdx.x & 31;
    if (gw >= NPAD) return;
    if (gw >= NROW){   // zero the pad rows every call (deterministic)
        #pragma unroll
        for (int q = 0; q < 8; q++) g_cfb[(size_t)gw*DD + lane + 32*q] = __float2bfloat16(0.0f);
        return;
    }
    int a = gw / VV, v = gw % VV;
    int b = a / CC;
    int p = g_idx[gw];
    const float* fb = feats + (size_t)b*DD*HWP + p;
    float vals[8]; float ss = 0.f;
    #pragma unroll
    for (int q = 0; q < 8; q++){
        vals[q] = fb[(size_t)(lane + 32*q)*HWP];
        ss += vals[q]*vals[q];
    }
    #pragma unroll
    for (int m = 16; m > 0; m >>= 1) ss += __shfl_xor_sync(0xffffffffu, ss, m);
    float sc = 1.0f / fmaxf(sqrtf(ss), 1e-12f);
    int n = v*AA + a;
    #pragma unroll
    for (int q = 0; q < 8; q++) g_cfb[(size_t)n*DD + lane + 32*q] = __float2bfloat16(vals[q]*sc);
}

// ---------------- kernel 4: HMMA (mma.sync bf16) Gram GEMM + contrastive epilogue ----------------
// SMEM: A tile 128x256 bf16 (64KB, 512B row pitch, 16B chunks XOR-swizzled), B same at +64KB.
#define SMEM_GEMM (2*128*512)

__global__ __launch_bounds__(256, 1) void k_gemm(){
    extern __shared__ char sm[];
    int t = threadIdx.x;
    int lane = t & 31, wid = t >> 5;
    int bi = blockIdx.y, bj = blockIdx.x;
    int i0 = bi*128, j0 = bj*128;

    // ---- stage both 128x256 bf16 tiles into swizzled SMEM ----
    const uint4* asrc = reinterpret_cast<const uint4*>(g_cfb + (size_t)i0*DD);
    const uint4* bsrc = reinterpret_cast<const uint4*>(g_cfb + (size_t)j0*DD);
    uint4* As = reinterpret_cast<uint4*>(sm);
    uint4* Bs = reinterpret_cast<uint4*>(sm + 65536);
    #pragma unroll
    for (int it = 0; it < 16; it++){
        int idx = t + it*256;          // 0..4095
        int r = idx >> 5, c = idx & 31;
        int sc = (c & 24) | ((c ^ r) & 7);
        As[r*32 + sc] = asrc[r*32 + c];
        Bs[r*32 + sc] = bsrc[r*32 + c];
    }
    __syncthreads();

    uint32_t sbase = smem_u32(sm);
    int wm = wid & 3, wn = wid >> 2;       // warp tile: rows wm*32, cols wn*64

    // per-lane ldmatrix row/col components
    int ra = wm*32 + (lane & 7) + ((lane >> 3) & 1) * 8;  // A row (mi=0), lanes16-31 -> k-half
    int ca = lane >> 4;                                    // A chunk offset (0/1)
    int rb = wn*64 + (lane & 7) + (lane >> 4) * 8;         // B row (nb=0)
    int cb = (lane >> 3) & 1;                              // B chunk offset (0/1)

    float acc[2][8][4];
    #pragma unroll
    for (int mi = 0; mi < 2; mi++)
        #pragma unroll
        for (int nj = 0; nj < 8; nj++)
            #pragma unroll
            for (int q = 0; q < 4; q++) acc[mi][nj][q] = 0.f;

    #pragma unroll
    for (int ks = 0; ks < 16; ks++){
        int c0 = ks*2;
        uint32_t a[2][4];
        #pragma unroll
        for (int mi = 0; mi < 2; mi++){
            int r = ra + mi*16;
            int c = c0 + ca;
            uint32_t addr = sbase + (uint32_t)(r*512 + (((c ^ r) & 7) | (c & 24))*16);
            ldsm4(a[mi], addr);
        }
        #pragma unroll
        for (int nb = 0; nb < 4; nb++){
            int r = rb + nb*16;
            int c = c0 + cb;
            uint32_t addr = sbase + 65536u + (uint32_t)(r*512 + (((c ^ r) & 7) | (c & 24))*16);
            uint32_t b[4];
            ldsm4(b, addr);
            mma16816(acc[0][2*nb],   a[0], b[0], b[1]);
            mma16816(acc[0][2*nb+1], a[0], b[2], b[3]);
            mma16816(acc[1][2*nb],   a[1], b[0], b[1]);
            mma16816(acc[1][2*nb+1], a[1], b[2], b[3]);
        }
    }

    // ---- epilogue ----
    // element (mi, nj, q): row = i0 + wm*32 + mi*16 + (q>>1)*8 + lane/4
    //                      col = j0 + wn*64 + nj*8 + (lane&3)*2 + (q&1)
    int r00 = i0 + wm*32 + (lane >> 2);
    int irow[2][2]; int im[2][2]; bool iok[2][2];
    #pragma unroll
    for (int mi = 0; mi < 2; mi++)
        #pragma unroll
        for (int h = 0; h < 2; h++){
            irow[mi][h] = r00 + mi*16 + h*8;
            iok[mi][h]  = irow[mi][h] < NROW;
            im[mi][h]   = irow[mi][h] % CC;
        }
    float rs[2][2] = {{0.f,0.f},{0.f,0.f}};
    int jc_base = j0 + wn*64 + (lane & 3)*2;
    #pragma unroll
    for (int nj = 0; nj < 8; nj++){
        int jc  = jc_base + nj*8;
        int jd0 = jc / CC;
        int jm0 = jc - jd0*CC;
        int jm1 = jm0 + 1, jd1 = jd0;
        if (jm1 == CC){ jm1 = 0; jd1++; }
        bool j0ok = (jc     < NROW);
        bool j1ok = (jc + 1 < NROW);
        #pragma unroll
        for (int mi = 0; mi < 2; mi++){
            #pragma unroll
            for (int h = 0; h < 2; h++){
                if (!iok[mi][h]) continue;
                int i  = irow[mi][h];
                int imm = im[mi][h];
                float l0 = acc[mi][nj][h*2+0] * 10.f;
                float l1 = acc[mi][nj][h*2+1] * 10.f;
                if (j0ok){
                    if (jm0 == imm) g_P[(size_t)i*POS + jd0] = l0;
                    else            rs[mi][h] += __expf(l0);
                }
                if (j1ok){
                    if (jm1 == imm) g_P[(size_t)i*POS + jd1] = l1;
                    else            rs[mi][h] += __expf(l1);
                }
            }
        }
    }
    // reduce across the 4 lanes sharing each row (lane&3)
    #pragma unroll
    for (int m = 1; m <= 2; m <<= 1)
        #pragma unroll
        for (int mi = 0; mi < 2; mi++)
            #pragma unroll
            for (int h = 0; h < 2; h++)
                rs[mi][h] += __shfl_xor_sync(0xffffffffu, rs[mi][h], m);
    // NOTE: warps wn=0 and wn=1 cover the SAME rows (different col halves) —
    // each writes its own partial slot [bj*2 + wn]; k_finalize sums all 132.
    if ((lane & 3) == 0){
        #pragma unroll
        for (int mi = 0; mi < 2; mi++)
            #pragma unroll
            for (int h = 0; h < 2; h++)
                if (iok[mi][h]) g_NSpart[(size_t)irow[mi][h]*NSW + bj*2 + wn] = rs[mi][h];
    }
}

// ---------------- kernel 5: per-row finalize ----------------
__global__ void k_finalize(){
    int gw   = (blockIdx.x*blockDim.x + threadIdx.x) >> 5;
    int lane = threadIdx.x & 31;
    if (gw >= NROW) return;
    float ns = 0.f;
    for (int jb = lane; jb < NSW; jb += 32) ns += g_NSpart[(size_t)gw*NSW + jb];
    #pragma unroll
    for (int m = 16; m > 0; m >>= 1) ns += __shfl_xor_sync(0xffffffffu, ns, m);
    int kself = gw / CC;    // self column index within positives
    float acc = 0.f;
    for (int k = lane; k < POS; k += 32){
        if (k == kself) continue;
        float l = g_P[(size_t)gw*POS + k];
        acc += l - __logf(__expf(l) + ns);
    }
    #pragma unroll
    for (int m = 16; m > 0; m >>= 1) acc += __shfl_xor_sync(0xffffffffu, acc, m);
    if (lane == 0) g_rowval[gw] = acc / 399.0f;
}

// ---------------- kernel 6: deterministic final reduction ----------------
__global__ void k_reduce(float* __restrict__ out){
    __shared__ float sh[256];
    int t = threadIdx.x;
    float s = 0.f;
    for (int i = t; i < NROW; i += 256) s += g_rowval[i];
    sh[t] = s; __syncthreads();
    for (int m = 128; m > 0; m >>= 1){
        if (t < m) sh[t] += sh[t+m];
        __syncthreads();
    }
    if (t == 0) out[0] = -(sh[0] / (float)NROW);
}

// ---------------- launch ----------------
extern "C" void kernel_launch(void* const* d_in, const int* in_sizes, int n_in,
                              void* d_out, int out_size){
    const float* feats   = nullptr;
    const float* predict = nullptr;
    const int*   labels  = nullptr;
    for (int i = 0; i < n_in; i++){
        if      (in_sizes[i] == BB*DD*HWP)   feats   = (const float*)d_in[i];
        else if (in_sizes[i] == BB*CC*4096)  predict = (const float*)d_in[i];
        else if (in_sizes[i] == BB*HWP)      labels  = (const int*)d_in[i];
    }
    cudaFuncSetAttribute(k_gemm, cudaFuncAttributeMaxDynamicSharedMemorySize, SMEM_GEMM);
    k_pred<<<(BB*HWP)/256, 256>>>(predict);
    k_select<<<AA, 256>>>(labels);
    k_gather<<<NPAD/8, 256>>>(feats);
    dim3 g4(NCB, NCB);
    k_gemm<<<g4, 256, SMEM_GEMM>>>();
    k_finalize<<<NROW/8, 256>>>();
    k_reduce<<<1, 256>>>((float*)d_out);
}

// round 13
// speedup vs baseline: 3.5417x; 1.1855x over previous
#include <cuda_runtime.h>
#include <cuda_bf16.h>
#include <cstdint>
#include <math.h>

// ---------------- problem constants ----------------
#define BB 4
#define CC 21
#define HWP 16384      // 128*128
#define DD 256
#define AA 84          // B*C anchor rows
#define VV 100         // views per anchor
#define NROW 8400      // A*V
#define NPAD 8448      // padded to 66*128
#define POS 400        // positives per row (incl. self)
#define NCB 66         // column blocks of 128
#define NSW (NCB*4)    // neg-sum partial slots per row
#define NTRI 2211      // 66*67/2 upper-triangle blocks

// ---------------- device scratch (static, no allocs) ----------------
__device__ int   g_pred[BB*HWP];
__device__ int   g_idx[AA*VV];
__device__ __align__(16) __nv_bfloat16 g_cfb[(size_t)NPAD*DD];  // normalized bf16 features [n][d]
__device__ float g_P[(size_t)NROW*POS];        // positive logits
__device__ float g_NSpart[(size_t)NROW*NSW];   // per (row, block-group, sub) neg-exp partials
__device__ float g_rowval[NROW];

// ---------------- helpers ----------------
__device__ __forceinline__ uint32_t smem_u32(const void* p){
    uint32_t a;
    asm("{ .reg .u64 t; cvta.to.shared.u64 t, %1; cvt.u32.u64 %0, t; }" : "=r"(a) : "l"(p));
    return a;
}
__device__ __forceinline__ void ldsm4(uint32_t* r, uint32_t addr){
    asm volatile("ldmatrix.sync.aligned.m8n8.x4.shared.b16 {%0,%1,%2,%3}, [%4];"
        : "=r"(r[0]), "=r"(r[1]), "=r"(r[2]), "=r"(r[3]) : "r"(addr));
}
__device__ __forceinline__ void mma16816(float* d, const uint32_t* a, uint32_t b0, uint32_t b1){
    asm volatile("mma.sync.aligned.m16n8k16.row.col.f32.bf16.bf16.f32 "
        "{%0,%1,%2,%3}, {%4,%5,%6,%7}, {%8,%9}, {%0,%1,%2,%3};"
        : "+f"(d[0]), "+f"(d[1]), "+f"(d[2]), "+f"(d[3])
        : "r"(a[0]), "r"(a[1]), "r"(a[2]), "r"(a[3]), "r"(b0), "r"(b1));
}
__device__ __forceinline__ void cpasync16(uint32_t saddr, const void* gaddr){
    asm volatile("cp.async.cg.shared.global [%0], [%1], 16;" :: "r"(saddr), "l"(gaddr));
}

// ---------------- kernel 1: bilinear upsample (64->128) + argmax over 21 classes ----------------
__global__ void k_pred(const float* __restrict__ predict){
    int tid = blockIdx.x*blockDim.x + threadIdx.x;
    if (tid >= BB*HWP) return;
    int b = tid >> 14;
    int p = tid & (HWP-1);
    int y = p >> 7, x = p & 127;
    float fy = fminf(fmaxf(0.5f*(float)y - 0.25f, 0.0f), 63.0f);
    float fx = fminf(fmaxf(0.5f*(float)x - 0.25f, 0.0f), 63.0f);
    int y0 = (int)fy, x0 = (int)fx;
    float wy = fy - (float)y0, wx = fx - (float)x0;
    int y1 = min(y0+1, 63), x1 = min(x0+1, 63);
    const float* pb = predict + (size_t)b*CC*4096;
    float best = -3.4e38f; int bc = 0;
    #pragma unroll
    for (int c = 0; c < CC; c++){
        const float* pc = pb + c*4096;
        float v00 = pc[y0*64+x0], v01 = pc[y0*64+x1];
        float v10 = pc[y1*64+x0], v11 = pc[y1*64+x1];
        float top = v00 + wx*(v01-v00);
        float bot = v10 + wx*(v11-v10);
        float v = top + wy*(bot-top);
        if (v > best){ best = v; bc = c; }
    }
    g_pred[tid] = bc;
}

// ---------------- kernel 2: per-(b,c) hard/easy selection (deterministic rank-based) ----------------
__global__ void k_select(const int* __restrict__ labels){
    __shared__ int sh_h[256], sh_e[256], sh_ph[256], sh_pe[256];
    __shared__ int s_hk, s_ek, s_S;
    int row = blockIdx.x;
    int b = row / CC, c = row % CC;
    int t = threadIdx.x;
    unsigned long long hbits = 0ull, ebits = 0ull;
    int base = b*HWP + t*64;
    for (int q = 0; q < 64; q++){
        int pr = g_pred[base+q];
        int lb = labels[base+q];
        if (pr == c){ if (lb == c) ebits |= (1ull<<q); else hbits |= (1ull<<q); }
    }
    sh_h[t] = __popcll(hbits); sh_e[t] = __popcll(ebits);
    __syncthreads();
    if (t == 0){
        int rh = 0, re = 0;
        for (int u = 0; u < 256; u++){ sh_ph[u]=rh; sh_pe[u]=re; rh+=sh_h[u]; re+=sh_e[u]; }
        int nh = rh, ne = re;
        int hk;
        if (nh >= 50 && ne >= 50) hk = 50;
        else if (nh >= 50)        hk = 100 - ne;
        else                      hk = nh;
        int ek = 100 - hk;
        s_hk = hk; s_ek = ek;
        s_S = min(nh, hk) + min(ne, ek);
    }
    __syncthreads();
    int hb = sh_ph[t], eb = sh_pe[t];
    int hk = s_hk, ek = s_ek, S = s_S;
    for (int q = 0; q < 64; q++){
        int p = t*64 + q;
        int slot;
        if ((hbits>>q)&1ull){
            if (hb < hk) slot = hb + min(eb, ek);
            else         slot = S + (p - min(hb,hk) - min(eb,ek));
            hb++;
        } else if ((ebits>>q)&1ull){
            if (eb < ek) slot = min(hb, hk) + eb;
            else         slot = S + (p - min(hb,hk) - min(eb,ek));
            eb++;
        } else {
            slot = S + (p - min(hb,hk) - min(eb,ek));
        }
        if (slot < VV) g_idx[row*VV + slot] = p;
    }
}

// ---------------- kernel 3: gather + L2-normalize -> bf16 cf[v*84+a][d] ----------------
__global__ void k_gather(const float* __restrict__ feats){
    int gw   = (blockIdx.x*blockDim.x + threadIdx.x) >> 5;
    int lane = threadIdx.x & 31;
    if (gw >= NPAD) return;
    if (gw >= NROW){   // zero the pad rows every call (deterministic)
        #pragma unroll
        for (int q = 0; q < 8; q++) g_cfb[(size_t)gw*DD + lane + 32*q] = __float2bfloat16(0.0f);
        return;
    }
    int a = gw / VV, v = gw % VV;
    int b = a / CC;
    int p = g_idx[gw];
    const float* fb = feats + (size_t)b*DD*HWP + p;
    float vals[8]; float ss = 0.f;
    #pragma unroll
    for (int q = 0; q < 8; q++){
        vals[q] = fb[(size_t)(lane + 32*q)*HWP];
        ss += vals[q]*vals[q];
    }
    #pragma unroll
    for (int m = 16; m > 0; m >>= 1) ss += __shfl_xor_sync(0xffffffffu, ss, m);
    float sc = 1.0f / fmaxf(sqrtf(ss), 1e-12f);
    int n = v*AA + a;
    #pragma unroll
    for (int q = 0; q < 8; q++) g_cfb[(size_t)n*DD + lane + 32*q] = __float2bfloat16(vals[q]*sc);
}

// ---------------- kernel 4: symmetric HMMA Gram GEMM + dual contrastive epilogue ----------------
// Upper-triangle blocks only (bi <= bj). Off-diagonal CTAs run the epilogue for
// both the row side (rows bi, cols bj) and the transposed side (rows bj, cols bi),
// reusing the same logits/exp values.
// SMEM: A tile 128x256 bf16 (64KB, 512B row pitch, XOR-swizzled 16B chunks), B at +64KB.
#define SMEM_GEMM (2*128*512)

__global__ __launch_bounds__(256, 1) void k_gemm(){
    extern __shared__ char sm[];
    int t = threadIdx.x;
    int lane = t & 31, wid = t >> 5;

    // decode upper-triangle block index -> (bi, bj), bi <= bj
    int m = blockIdx.x;
    int bi = (int)((133.0 - sqrt(17689.0 - 8.0*(double)m)) * 0.5);
    // fixup (f(bi) = bi*(133-bi)/2)
    while ((bi+1)*(133-(bi+1))/2 <= m) bi++;
    while (bi*(133-bi)/2 > m) bi--;
    int bj = bi + (m - bi*(133-bi)/2);
    int i0 = bi*128, j0 = bj*128;
    bool offdiag = (bi != bj);

    // ---- stage both 128x256 bf16 tiles into swizzled SMEM via cp.async ----
    uint32_t sbase = smem_u32(sm);
    {
        const char* ag = (const char*)(g_cfb + (size_t)i0*DD);
        const char* bg = (const char*)(g_cfb + (size_t)j0*DD);
        #pragma unroll
        for (int it = 0; it < 16; it++){
            int idx = t + it*256;          // 0..4095
            int r = idx >> 5, c = idx & 31;
            int sc = (c & 24) | ((c ^ r) & 7);
            uint32_t so = (uint32_t)((r*32 + sc)*16);
            size_t   go = (size_t)(r*32 + c)*16;
            cpasync16(sbase + so,           ag + go);
            cpasync16(sbase + 65536u + so,  bg + go);
        }
        asm volatile("cp.async.commit_group;" ::: "memory");
        asm volatile("cp.async.wait_group 0;" ::: "memory");
    }
    __syncthreads();

    int wm = wid & 3, wn = wid >> 2;       // warp tile: rows wm*32, cols wn*64

    // per-lane ldmatrix row/col components
    int ra = wm*32 + (lane & 7) + ((lane >> 3) & 1) * 8;
    int ca = lane >> 4;
    int rb = wn*64 + (lane & 7) + (lane >> 4) * 8;
    int cb = (lane >> 3) & 1;

    float acc[2][8][4];
    #pragma unroll
    for (int mi = 0; mi < 2; mi++)
        #pragma unroll
        for (int nj = 0; nj < 8; nj++)
            #pragma unroll
            for (int q = 0; q < 4; q++) acc[mi][nj][q] = 0.f;

    #pragma unroll
    for (int ks = 0; ks < 16; ks++){
        int c0 = ks*2;
        uint32_t a[2][4];
        #pragma unroll
        for (int mi = 0; mi < 2; mi++){
            int r = ra + mi*16;
            int c = c0 + ca;
            uint32_t addr = sbase + (uint32_t)(r*512 + (((c ^ r) & 7) | (c & 24))*16);
            ldsm4(a[mi], addr);
        }
        #pragma unroll
        for (int nb = 0; nb < 4; nb++){
            int r = rb + nb*16;
            int c = c0 + cb;
            uint32_t addr = sbase + 65536u + (uint32_t)(r*512 + (((c ^ r) & 7) | (c & 24))*16);
            uint32_t b[4];
            ldsm4(b, addr);
            mma16816(acc[0][2*nb],   a[0], b[0], b[1]);
            mma16816(acc[0][2*nb+1], a[0], b[2], b[3]);
            mma16816(acc[1][2*nb],   a[1], b[0], b[1]);
            mma16816(acc[1][2*nb+1], a[1], b[2], b[3]);
        }
    }

    // ---- dual epilogue ----
    // element (mi, nj, q): row = i0 + wm*32 + mi*16 + (q>>1)*8 + lane/4
    //                      col = j0 + wn*64 + nj*8 + (lane&3)*2 + (q&1)
    int r00 = i0 + wm*32 + (lane >> 2);
    int irow[2][2]; int im[2][2]; int idv[2][2]; bool iok[2][2];
    #pragma unroll
    for (int mi = 0; mi < 2; mi++)
        #pragma unroll
        for (int h = 0; h < 2; h++){
            irow[mi][h] = r00 + mi*16 + h*8;
            iok[mi][h]  = irow[mi][h] < NROW;
            idv[mi][h]  = irow[mi][h] / CC;
            im[mi][h]   = irow[mi][h] - idv[mi][h]*CC;
        }
    float rs[2][2] = {{0.f,0.f},{0.f,0.f}};
    float rsc[16];
    #pragma unroll
    for (int q = 0; q < 16; q++) rsc[q] = 0.f;

    int jc_base = j0 + wn*64 + (lane & 3)*2;
    #pragma unroll
    for (int nj = 0; nj < 8; nj++){
        int jc  = jc_base + nj*8;
        int jd0 = jc / CC;
        int jm0 = jc - jd0*CC;
        int jm1 = jm0 + 1, jd1 = jd0;
        if (jm1 == CC){ jm1 = 0; jd1++; }
        bool j0ok = (jc     < NROW);
        bool j1ok = (jc + 1 < NROW);
        #pragma unroll
        for (int mi = 0; mi < 2; mi++){
            #pragma unroll
            for (int h = 0; h < 2; h++){
                if (!iok[mi][h]) continue;
                int i   = irow[mi][h];
                int imm = im[mi][h];
                float l0 = acc[mi][nj][h*2+0] * 10.f;
                float l1 = acc[mi][nj][h*2+1] * 10.f;
                if (j0ok){
                    if (jm0 == imm){
                        g_P[(size_t)i*POS + jd0] = l0;
                        if (offdiag) g_P[(size_t)jc*POS + idv[mi][h]] = l0;
                    } else {
                        float e = __expf(l0);
                        rs[mi][h]    += e;
                        rsc[nj*2+0]  += e;
                    }
                }
                if (j1ok){
                    if (jm1 == imm){
                        g_P[(size_t)i*POS + jd1] = l1;
                        if (offdiag) g_P[(size_t)(jc+1)*POS + idv[mi][h]] = l1;
                    } else {
                        float e = __expf(l1);
                        rs[mi][h]    += e;
                        rsc[nj*2+1]  += e;
                    }
                }
            }
        }
    }

    // direct side: reduce across 4 lanes sharing each row (strides 1,2)
    #pragma unroll
    for (int ms = 1; ms <= 2; ms <<= 1)
        #pragma unroll
        for (int mi = 0; mi < 2; mi++)
            #pragma unroll
            for (int h = 0; h < 2; h++)
                rs[mi][h] += __shfl_xor_sync(0xffffffffu, rs[mi][h], ms);
    if ((lane & 3) == 0){
        #pragma unroll
        for (int mi = 0; mi < 2; mi++)
            #pragma unroll
            for (int h = 0; h < 2; h++)
                if (iok[mi][h]){
                    g_NSpart[(size_t)irow[mi][h]*NSW + bj*4 + wn]     = rs[mi][h];
                    g_NSpart[(size_t)irow[mi][h]*NSW + bj*4 + 2 + wn] = 0.f;  // unused subs
                }
    }

    // transposed side: reduce columns across the 8 row-groups (strides 4,8,16)
    if (offdiag){
        #pragma unroll
        for (int ms = 4; ms <= 16; ms <<= 1)
            #pragma unroll
            for (int q = 0; q < 16; q++)
                rsc[q] += __shfl_xor_sync(0xffffffffu, rsc[q], ms);
        if ((lane >> 2) == 0){
            #pragma unroll
            for (int nj = 0; nj < 8; nj++){
                #pragma unroll
                for (int p = 0; p < 2; p++){
                    int j = jc_base + nj*8 + p;
                    if (j < NROW) g_NSpart[(size_t)j*NSW + bi*4 + wm] = rsc[nj*2+p];
                }
            }
        }
    }
}

// ---------------- kernel 5: per-row finalize ----------------
__global__ void k_finalize(){
    int gw   = (blockIdx.x*blockDim.x + threadIdx.x) >> 5;
    int lane = threadIdx.x & 31;
    if (gw >= NROW) return;
    float ns = 0.f;
    for (int jb = lane; jb < NSW; jb += 32) ns += g_NSpart[(size_t)gw*NSW + jb];
    #pragma unroll
    for (int m = 16; m > 0; m >>= 1) ns += __shfl_xor_sync(0xffffffffu, ns, m);
    int kself = gw / CC;    // self column index within positives
    float acc = 0.f;
    for (int k = lane; k < POS; k += 32){
        if (k == kself) continue;
        float l = g_P[(size_t)gw*POS + k];
        acc += l - __logf(__expf(l) + ns);
    }
    #pragma unroll
    for (int m = 16; m > 0; m >>= 1) acc += __shfl_xor_sync(0xffffffffu, acc, m);
    if (lane == 0) g_rowval[gw] = acc / 399.0f;
}

// ---------------- kernel 6: deterministic final reduction ----------------
__global__ void k_reduce(float* __restrict__ out){
    __shared__ float sh[256];
    int t = threadIdx.x;
    float s = 0.f;
    for (int i = t; i < NROW; i += 256) s += g_rowval[i];
    sh[t] = s; __syncthreads();
    for (int m = 128; m > 0; m >>= 1){
        if (t < m) sh[t] += sh[t+m];
        __syncthreads();
    }
    if (t == 0) out[0] = -(sh[0] / (float)NROW);
}

// ---------------- launch ----------------
extern "C" void kernel_launch(void* const* d_in, const int* in_sizes, int n_in,
                              void* d_out, int out_size){
    const float* feats   = nullptr;
    const float* predict = nullptr;
    const int*   labels  = nullptr;
    for (int i = 0; i < n_in; i++){
        if      (in_sizes[i] == BB*DD*HWP)   feats   = (const float*)d_in[i];
        else if (in_sizes[i] == BB*CC*4096)  predict = (const float*)d_in[i];
        else if (in_sizes[i] == BB*HWP)      labels  = (const int*)d_in[i];
    }
    cudaFuncSetAttribute(k_gemm, cudaFuncAttributeMaxDynamicSharedMemorySize, SMEM_GEMM);
    k_pred<<<(BB*HWP)/256, 256>>>(predict);
    k_select<<<AA, 256>>>(labels);
    k_gather<<<NPAD/8, 256>>>(feats);
    k_gemm<<<NTRI, 256, SMEM_GEMM>>>();
    k_finalize<<<NROW/8, 256>>>();
    k_reduce<<<1, 256>>>((float*)d_out);
}

// round 14
// speedup vs baseline: 5.0185x; 1.4170x over previous
#include <cuda_runtime.h>
#include <cuda_bf16.h>
#include <cstdint>
#include <math.h>

// ---------------- problem constants ----------------
#define BB 4
#define CC 21
#define HWP 16384      // 128*128
#define DD 256
#define AA 84          // B*C anchor rows
#define VV 100         // views per anchor
#define NROW 8400      // A*V
#define NPAD 8448      // padded to 66*128
#define POS 400        // positives per row (incl. self)
#define NCB 66         // column blocks of 128
#define NSW (NCB*4)    // neg-sum partial slots per row
#define NTRI 2211      // 66*67/2 upper-triangle blocks

// ---------------- device scratch (static, no allocs) ----------------
__device__ int   g_pred[BB*HWP];
__device__ int   g_idx[AA*VV];
__device__ __align__(16) __nv_bfloat16 g_cfb[(size_t)NPAD*DD];  // normalized bf16 features [n][d]
__device__ float g_P[(size_t)NROW*POS];        // positive logits
__device__ float g_NSpart[(size_t)NROW*NSW];   // per (row, block-group, sub) neg-exp partials
__device__ float g_rowval[NROW];

// ---------------- helpers ----------------
__device__ __forceinline__ uint32_t smem_u32(const void* p){
    uint32_t a;
    asm("{ .reg .u64 t; cvta.to.shared.u64 t, %1; cvt.u32.u64 %0, t; }" : "=r"(a) : "l"(p));
    return a;
}
__device__ __forceinline__ void ldsm4(uint32_t* r, uint32_t addr){
    asm volatile("ldmatrix.sync.aligned.m8n8.x4.shared.b16 {%0,%1,%2,%3}, [%4];"
        : "=r"(r[0]), "=r"(r[1]), "=r"(r[2]), "=r"(r[3]) : "r"(addr));
}
__device__ __forceinline__ void mma16816(float* d, const uint32_t* a, uint32_t b0, uint32_t b1){
    asm volatile("mma.sync.aligned.m16n8k16.row.col.f32.bf16.bf16.f32 "
        "{%0,%1,%2,%3}, {%4,%5,%6,%7}, {%8,%9}, {%0,%1,%2,%3};"
        : "+f"(d[0]), "+f"(d[1]), "+f"(d[2]), "+f"(d[3])
        : "r"(a[0]), "r"(a[1]), "r"(a[2]), "r"(a[3]), "r"(b0), "r"(b1));
}
__device__ __forceinline__ void cpasync16(uint32_t saddr, const void* gaddr){
    asm volatile("cp.async.cg.shared.global [%0], [%1], 16;" :: "r"(saddr), "l"(gaddr));
}

// ---------------- kernel 1: bilinear upsample (64->128) + argmax over 21 classes ----------------
__global__ void k_pred(const float* __restrict__ predict){
    int tid = blockIdx.x*blockDim.x + threadIdx.x;
    if (tid >= BB*HWP) return;
    int b = tid >> 14;
    int p = tid & (HWP-1);
    int y = p >> 7, x = p & 127;
    float fy = fminf(fmaxf(0.5f*(float)y - 0.25f, 0.0f), 63.0f);
    float fx = fminf(fmaxf(0.5f*(float)x - 0.25f, 0.0f), 63.0f);
    int y0 = (int)fy, x0 = (int)fx;
    float wy = fy - (float)y0, wx = fx - (float)x0;
    int y1 = min(y0+1, 63), x1 = min(x0+1, 63);
    const float* pb = predict + (size_t)b*CC*4096;
    float best = -3.4e38f; int bc = 0;
    #pragma unroll
    for (int c = 0; c < CC; c++){
        const float* pc = pb + c*4096;
        float v00 = pc[y0*64+x0], v01 = pc[y0*64+x1];
        float v10 = pc[y1*64+x0], v11 = pc[y1*64+x1];
        float top = v00 + wx*(v01-v00);
        float bot = v10 + wx*(v11-v10);
        float v = top + wy*(bot-top);
        if (v > best){ best = v; bc = c; }
    }
    g_pred[tid] = bc;
}

// ---------------- kernel 2: per-(b,c) hard/easy selection (deterministic rank-based) ----------------
__global__ void k_select(const int* __restrict__ labels){
    __shared__ int sh_h[256], sh_e[256], sh_ph[256], sh_pe[256];
    __shared__ int s_hk, s_ek, s_S;
    int row = blockIdx.x;
    int b = row / CC, c = row % CC;
    int t = threadIdx.x;
    unsigned long long hbits = 0ull, ebits = 0ull;
    int base = b*HWP + t*64;
    for (int q = 0; q < 64; q++){
        int pr = g_pred[base+q];
        int lb = labels[base+q];
        if (pr == c){ if (lb == c) ebits |= (1ull<<q); else hbits |= (1ull<<q); }
    }
    sh_h[t] = __popcll(hbits); sh_e[t] = __popcll(ebits);
    __syncthreads();
    if (t == 0){
        int rh = 0, re = 0;
        for (int u = 0; u < 256; u++){ sh_ph[u]=rh; sh_pe[u]=re; rh+=sh_h[u]; re+=sh_e[u]; }
        int nh = rh, ne = re;
        int hk;
        if (nh >= 50 && ne >= 50) hk = 50;
        else if (nh >= 50)        hk = 100 - ne;
        else                      hk = nh;
        int ek = 100 - hk;
        s_hk = hk; s_ek = ek;
        s_S = min(nh, hk) + min(ne, ek);
    }
    __syncthreads();
    int hb = sh_ph[t], eb = sh_pe[t];
    int hk = s_hk, ek = s_ek, S = s_S;
    for (int q = 0; q < 64; q++){
        int p = t*64 + q;
        int slot;
        if ((hbits>>q)&1ull){
            if (hb < hk) slot = hb + min(eb, ek);
            else         slot = S + (p - min(hb,hk) - min(eb,ek));
            hb++;
        } else if ((ebits>>q)&1ull){
            if (eb < ek) slot = min(hb, hk) + eb;
            else         slot = S + (p - min(hb,hk) - min(eb,ek));
            eb++;
        } else {
            slot = S + (p - min(hb,hk) - min(eb,ek));
        }
        if (slot < VV) g_idx[row*VV + slot] = p;
    }
}

// ---------------- kernel 3: gather + L2-normalize -> bf16 cf[v*84+a][d] ----------------
__global__ void k_gather(const float* __restrict__ feats){
    int gw   = (blockIdx.x*blockDim.x + threadIdx.x) >> 5;
    int lane = threadIdx.x & 31;
    if (gw >= NPAD) return;
    if (gw >= NROW){   // zero the pad rows every call (deterministic)
        #pragma unroll
        for (int q = 0; q < 8; q++) g_cfb[(size_t)gw*DD + lane + 32*q] = __float2bfloat16(0.0f);
        return;
    }
    int a = gw / VV, v = gw % VV;
    int b = a / CC;
    int p = g_idx[gw];
    const float* fb = feats + (size_t)b*DD*HWP + p;
    float vals[8]; float ss = 0.f;
    #pragma unroll
    for (int q = 0; q < 8; q++){
        vals[q] = fb[(size_t)(lane + 32*q)*HWP];
        ss += vals[q]*vals[q];
    }
    #pragma unroll
    for (int m = 16; m > 0; m >>= 1) ss += __shfl_xor_sync(0xffffffffu, ss, m);
    float sc = 1.0f / fmaxf(sqrtf(ss), 1e-12f);
    int n = v*AA + a;
    #pragma unroll
    for (int q = 0; q < 8; q++) g_cfb[(size_t)n*DD + lane + 32*q] = __float2bfloat16(vals[q]*sc);
}

// ---------------- kernel 4: symmetric HMMA Gram GEMM, K-pipelined, 2 CTA/SM ----------------
// Upper-triangle blocks only (bi <= bj). K=256 split into 4 chunks of 64,
// double-buffered in 64KB smem (2 stages x (A 16KB + B 16KB)) via cp.async.
// Off-diagonal CTAs run the epilogue for both the row side and the transposed side.
#define SMEM_GEMM 65536
#define STG 32768       // stage stride
#define BOFF 16384      // B tile offset within stage

__global__ __launch_bounds__(256, 2) void k_gemm(){
    extern __shared__ char sm[];
    int t = threadIdx.x;
    int lane = t & 31, wid = t >> 5;

    // decode upper-triangle block index -> (bi, bj), bi <= bj
    int m = blockIdx.x;
    int bi = (int)((133.0 - sqrt(17689.0 - 8.0*(double)m)) * 0.5);
    while ((bi+1)*(133-(bi+1))/2 <= m) bi++;
    while (bi*(133-bi)/2 > m) bi--;
    int bj = bi + (m - bi*(133-bi)/2);
    int i0 = bi*128, j0 = bj*128;
    bool offdiag = (bi != bj);

    uint32_t sbase = smem_u32(sm);
    const char* ag = (const char*)(g_cfb + (size_t)i0*DD);
    const char* bg = (const char*)(g_cfb + (size_t)j0*DD);

    // per-chunk loader: 128 rows x 64 bf16 (128B/row), XOR-swizzled 16B chunks
    auto prefetch = [&](int kc, int st){
        uint32_t sb = sbase + st*STG;
        size_t  koff = (size_t)kc*128;   // 64 bf16 = 128 bytes
        #pragma unroll
        for (int u = 0; u < 4; u++){
            int idx = t + u*256;         // 0..1023
            int r = idx >> 3, c = idx & 7;
            uint32_t so = (uint32_t)(r*128 + (((c ^ r) & 7))*16);
            size_t   go = (size_t)r*512 + koff + (size_t)c*16;
            cpasync16(sb + so,         ag + go);
            cpasync16(sb + BOFF + so,  bg + go);
        }
        asm volatile("cp.async.commit_group;" ::: "memory");
    };

    prefetch(0, 0);

    int wm = wid & 3, wn = wid >> 2;       // warp tile: rows wm*32, cols wn*64

    // per-lane ldmatrix row/col components
    int ra = wm*32 + (lane & 7) + ((lane >> 3) & 1) * 8;
    int ca = lane >> 4;
    int rb = wn*64 + (lane & 7) + (lane >> 4) * 8;
    int cb = (lane >> 3) & 1;

    float acc[2][8][4];
    #pragma unroll
    for (int mi = 0; mi < 2; mi++)
        #pragma unroll
        for (int nj = 0; nj < 8; nj++)
            #pragma unroll
            for (int q = 0; q < 4; q++) acc[mi][nj][q] = 0.f;

    #pragma unroll
    for (int kc = 0; kc < 4; kc++){
        int st = kc & 1;
        if (kc < 3) prefetch(kc+1, st^1);
        if (kc < 3) asm volatile("cp.async.wait_group 1;" ::: "memory");
        else        asm volatile("cp.async.wait_group 0;" ::: "memory");
        __syncthreads();
        uint32_t sb = sbase + st*STG;
        #pragma unroll
        for (int ks = 0; ks < 4; ks++){
            int c0 = ks*2;
            uint32_t a[2][4];
            #pragma unroll
            for (int mi = 0; mi < 2; mi++){
                int r = ra + mi*16;
                int c = c0 + ca;
                uint32_t addr = sb + (uint32_t)(r*128 + (((c ^ r) & 7))*16);
                ldsm4(a[mi], addr);
            }
            #pragma unroll
            for (int nb = 0; nb < 4; nb++){
                int r = rb + nb*16;
                int c = c0 + cb;
                uint32_t addr = sb + BOFF + (uint32_t)(r*128 + (((c ^ r) & 7))*16);
                uint32_t b[4];
                ldsm4(b, addr);
                mma16816(acc[0][2*nb],   a[0], b[0], b[1]);
                mma16816(acc[0][2*nb+1], a[0], b[2], b[3]);
                mma16816(acc[1][2*nb],   a[1], b[0], b[1]);
                mma16816(acc[1][2*nb+1], a[1], b[2], b[3]);
            }
        }
        __syncthreads();   // stage reuse guard for the next-next prefetch
    }

    // ---- dual epilogue ----
    // element (mi, nj, q): row = i0 + wm*32 + mi*16 + (q>>1)*8 + lane/4
    //                      col = j0 + wn*64 + nj*8 + (lane&3)*2 + (q&1)
    int r00 = i0 + wm*32 + (lane >> 2);
    int irow[2][2]; int im[2][2]; int idv[2][2]; bool iok[2][2];
    #pragma unroll
    for (int mi = 0; mi < 2; mi++)
        #pragma unroll
        for (int h = 0; h < 2; h++){
            irow[mi][h] = r00 + mi*16 + h*8;
            iok[mi][h]  = irow[mi][h] < NROW;
            idv[mi][h]  = irow[mi][h] / CC;
            im[mi][h]   = irow[mi][h] - idv[mi][h]*CC;
        }
    float rs[2][2] = {{0.f,0.f},{0.f,0.f}};
    float rsc[16];
    #pragma unroll
    for (int q = 0; q < 16; q++) rsc[q] = 0.f;

    int jc_base = j0 + wn*64 + (lane & 3)*2;
    #pragma unroll
    for (int nj = 0; nj < 8; nj++){
        int jc  = jc_base + nj*8;
        int jd0 = jc / CC;
        int jm0 = jc - jd0*CC;
        int jm1 = jm0 + 1, jd1 = jd0;
        if (jm1 == CC){ jm1 = 0; jd1++; }
        bool j0ok = (jc     < NROW);
        bool j1ok = (jc + 1 < NROW);
        #pragma unroll
        for (int mi = 0; mi < 2; mi++){
            #pragma unroll
            for (int h = 0; h < 2; h++){
                if (!iok[mi][h]) continue;
                int i   = irow[mi][h];
                int imm = im[mi][h];
                float l0 = acc[mi][nj][h*2+0] * 10.f;
                float l1 = acc[mi][nj][h*2+1] * 10.f;
                if (j0ok){
                    if (jm0 == imm){
                        g_P[(size_t)i*POS + jd0] = l0;
                        if (offdiag) g_P[(size_t)jc*POS + idv[mi][h]] = l0;
                    } else {
                        float e = __expf(l0);
                        rs[mi][h]    += e;
                        rsc[nj*2+0]  += e;
                    }
                }
                if (j1ok){
                    if (jm1 == imm){
                        g_P[(size_t)i*POS + jd1] = l1;
                        if (offdiag) g_P[(size_t)(jc+1)*POS + idv[mi][h]] = l1;
                    } else {
                        float e = __expf(l1);
                        rs[mi][h]    += e;
                        rsc[nj*2+1]  += e;
                    }
                }
            }
        }
    }

    // direct side: reduce across 4 lanes sharing each row (strides 1,2)
    #pragma unroll
    for (int ms = 1; ms <= 2; ms <<= 1)
        #pragma unroll
        for (int mi = 0; mi < 2; mi++)
            #pragma unroll
            for (int h = 0; h < 2; h++)
                rs[mi][h] += __shfl_xor_sync(0xffffffffu, rs[mi][h], ms);
    if ((lane & 3) == 0){
        #pragma unroll
        for (int mi = 0; mi < 2; mi++)
            #pragma unroll
            for (int h = 0; h < 2; h++)
                if (iok[mi][h]){
                    g_NSpart[(size_t)irow[mi][h]*NSW + bj*4 + wn]     = rs[mi][h];
                    g_NSpart[(size_t)irow[mi][h]*NSW + bj*4 + 2 + wn] = 0.f;  // unused subs
                }
    }

    // transposed side: reduce columns across the 8 row-groups (strides 4,8,16)
    if (offdiag){
        #pragma unroll
        for (int ms = 4; ms <= 16; ms <<= 1)
            #pragma unroll
            for (int q = 0; q < 16; q++)
                rsc[q] += __shfl_xor_sync(0xffffffffu, rsc[q], ms);
        if ((lane >> 2) == 0){
            #pragma unroll
            for (int nj = 0; nj < 8; nj++){
                #pragma unroll
                for (int p = 0; p < 2; p++){
                    int j = jc_base + nj*8 + p;
                    if (j < NROW) g_NSpart[(size_t)j*NSW + bi*4 + wm] = rsc[nj*2+p];
                }
            }
        }
    }
}

// ---------------- kernel 5: per-row finalize ----------------
__global__ void k_finalize(){
    int gw   = (blockIdx.x*blockDim.x + threadIdx.x) >> 5;
    int lane = threadIdx.x & 31;
    if (gw >= NROW) return;
    float ns = 0.f;
    for (int jb = lane; jb < NSW; jb += 32) ns += g_NSpart[(size_t)gw*NSW + jb];
    #pragma unroll
    for (int m = 16; m > 0; m >>= 1) ns += __shfl_xor_sync(0xffffffffu, ns, m);
    int kself = gw / CC;    // self column index within positives
    float acc = 0.f;
    for (int k = lane; k < POS; k += 32){
        if (k == kself) continue;
        float l = g_P[(size_t)gw*POS + k];
        acc += l - __logf(__expf(l) + ns);
    }
    #pragma unroll
    for (int m = 16; m > 0; m >>= 1) acc += __shfl_xor_sync(0xffffffffu, acc, m);
    if (lane == 0) g_rowval[gw] = acc / 399.0f;
}

// ---------------- kernel 6: deterministic final reduction ----------------
__global__ void k_reduce(float* __restrict__ out){
    __shared__ float sh[256];
    int t = threadIdx.x;
    float s = 0.f;
    for (int i = t; i < NROW; i += 256) s += g_rowval[i];
    sh[t] = s; __syncthreads();
    for (int m = 128; m > 0; m >>= 1){
        if (t < m) sh[t] += sh[t+m];
        __syncthreads();
    }
    if (t == 0) out[0] = -(sh[0] / (float)NROW);
}

// ---------------- launch ----------------
extern "C" void kernel_launch(void* const* d_in, const int* in_sizes, int n_in,
                              void* d_out, int out_size){
    const float* feats   = nullptr;
    const float* predict = nullptr;
    const int*   labels  = nullptr;
    for (int i = 0; i < n_in; i++){
        if      (in_sizes[i] == BB*DD*HWP)   feats   = (const float*)d_in[i];
        else if (in_sizes[i] == BB*CC*4096)  predict = (const float*)d_in[i];
        else if (in_sizes[i] == BB*HWP)      labels  = (const int*)d_in[i];
    }
    cudaFuncSetAttribute(k_gemm, cudaFuncAttributeMaxDynamicSharedMemorySize, SMEM_GEMM);
    k_pred<<<(BB*HWP)/256, 256>>>(predict);
    k_select<<<AA, 256>>>(labels);
    k_gather<<<NPAD/8, 256>>>(feats);
    k_gemm<<<NTRI, 256, SMEM_GEMM>>>();
    k_finalize<<<NROW/8, 256>>>();
    k_reduce<<<1, 256>>>((float*)d_out);
}

// round 15
// speedup vs baseline: 6.3564x; 1.2666x over previous
#include <cuda_runtime.h>
#include <cuda_bf16.h>
#include <cstdint>
#include <math.h>

// ---------------- problem constants ----------------
#define BB 4
#define CC 21
#define HWP 16384      // 128*128
#define DD 256
#define AA 84          // B*C anchor rows
#define VV 100         // views per anchor
#define NROW 8400      // A*V
#define NPAD 8448      // padded to 66*128
#define POS 400        // positives per row (incl. self)
#define NCB 66         // column blocks of 128
#define NSW (NCB*4)    // neg-sum partial slots per row
#define NTRI 2211      // 66*67/2 upper-triangle blocks
#define NPADCOL 48.0f  // pad columns contribute exp(0)=1 each to every row sum

// ---------------- device scratch (static, no allocs) ----------------
__device__ int   g_pred[BB*HWP];
__device__ int   g_idx[AA*VV];
__device__ __align__(16) __nv_bfloat16 g_cfb[(size_t)NPAD*DD];  // class-major normalized bf16 features
__device__ float g_P[(size_t)NROW*POS];        // positive logits (row-class band)
__device__ float g_NSpart[(size_t)NROW*NSW];   // per (row, block-group, sub) exp-sum partials
__device__ float g_rowval[NROW];
__device__ int   g_cnt;                        // last-block counter (reset by last block)

// ---------------- helpers ----------------
__device__ __forceinline__ uint32_t smem_u32(const void* p){
    uint32_t a;
    asm("{ .reg .u64 t; cvta.to.shared.u64 t, %1; cvt.u32.u64 %0, t; }" : "=r"(a) : "l"(p));
    return a;
}
__device__ __forceinline__ void ldsm4(uint32_t* r, uint32_t addr){
    asm volatile("ldmatrix.sync.aligned.m8n8.x4.shared.b16 {%0,%1,%2,%3}, [%4];"
        : "=r"(r[0]), "=r"(r[1]), "=r"(r[2]), "=r"(r[3]) : "r"(addr));
}
__device__ __forceinline__ void mma16816(float* d, const uint32_t* a, uint32_t b0, uint32_t b1){
    asm volatile("mma.sync.aligned.m16n8k16.row.col.f32.bf16.bf16.f32 "
        "{%0,%1,%2,%3}, {%4,%5,%6,%7}, {%8,%9}, {%0,%1,%2,%3};"
        : "+f"(d[0]), "+f"(d[1]), "+f"(d[2]), "+f"(d[3])
        : "r"(a[0]), "r"(a[1]), "r"(a[2]), "r"(a[3]), "r"(b0), "r"(b1));
}
__device__ __forceinline__ void cpasync16(uint32_t saddr, const void* gaddr){
    asm volatile("cp.async.cg.shared.global [%0], [%1], 16;" :: "r"(saddr), "l"(gaddr));
}
__device__ __forceinline__ float fex2(float x){
    float r;
    asm("ex2.approx.f32 %0, %1;" : "=f"(r) : "f"(x));
    return r;
}

// ---------------- kernel 1: bilinear upsample (64->128) + argmax over 21 classes ----------------
__global__ void k_pred(const float* __restrict__ predict){
    int tid = blockIdx.x*blockDim.x + threadIdx.x;
    if (tid >= BB*HWP) return;
    int b = tid >> 14;
    int p = tid & (HWP-1);
    int y = p >> 7, x = p & 127;
    float fy = fminf(fmaxf(0.5f*(float)y - 0.25f, 0.0f), 63.0f);
    float fx = fminf(fmaxf(0.5f*(float)x - 0.25f, 0.0f), 63.0f);
    int y0 = (int)fy, x0 = (int)fx;
    float wy = fy - (float)y0, wx = fx - (float)x0;
    int y1 = min(y0+1, 63), x1 = min(x0+1, 63);
    const float* pb = predict + (size_t)b*CC*4096;
    float best = -3.4e38f; int bc = 0;
    #pragma unroll
    for (int c = 0; c < CC; c++){
        const float* pc = pb + c*4096;
        float v00 = pc[y0*64+x0], v01 = pc[y0*64+x1];
        float v10 = pc[y1*64+x0], v11 = pc[y1*64+x1];
        float top = v00 + wx*(v01-v00);
        float bot = v10 + wx*(v11-v10);
        float v = top + wy*(bot-top);
        if (v > best){ best = v; bc = c; }
    }
    g_pred[tid] = bc;
}

// ---------------- kernel 2: per-(b,c) hard/easy selection (deterministic rank-based) ----------------
__global__ void k_select(const int* __restrict__ labels){
    __shared__ int sh_h[256], sh_e[256], sh_ph[256], sh_pe[256];
    __shared__ int s_hk, s_ek, s_S;
    int row = blockIdx.x;
    int b = row / CC, c = row % CC;
    int t = threadIdx.x;
    unsigned long long hbits = 0ull, ebits = 0ull;
    int base = b*HWP + t*64;
    for (int q = 0; q < 64; q++){
        int pr = g_pred[base+q];
        int lb = labels[base+q];
        if (pr == c){ if (lb == c) ebits |= (1ull<<q); else hbits |= (1ull<<q); }
    }
    sh_h[t] = __popcll(hbits); sh_e[t] = __popcll(ebits);
    __syncthreads();
    if (t == 0){
        int rh = 0, re = 0;
        for (int u = 0; u < 256; u++){ sh_ph[u]=rh; sh_pe[u]=re; rh+=sh_h[u]; re+=sh_e[u]; }
        int nh = rh, ne = re;
        int hk;
        if (nh >= 50 && ne >= 50) hk = 50;
        else if (nh >= 50)        hk = 100 - ne;
        else                      hk = nh;
        int ek = 100 - hk;
        s_hk = hk; s_ek = ek;
        s_S = min(nh, hk) + min(ne, ek);
    }
    __syncthreads();
    int hb = sh_ph[t], eb = sh_pe[t];
    int hk = s_hk, ek = s_ek, S = s_S;
    for (int q = 0; q < 64; q++){
        int p = t*64 + q;
        int slot;
        if ((hbits>>q)&1ull){
            if (hb < hk) slot = hb + min(eb, ek);
            else         slot = S + (p - min(hb,hk) - min(eb,ek));
            hb++;
        } else if ((ebits>>q)&1ull){
            if (eb < ek) slot = min(hb, hk) + eb;
            else         slot = S + (p - min(hb,hk) - min(eb,ek));
            eb++;
        } else {
            slot = S + (p - min(hb,hk) - min(eb,ek));
        }
        if (slot < VV) g_idx[row*VV + slot] = p;
    }
}

// ---------------- kernel 3: gather + L2-normalize -> bf16, CLASS-MAJOR rows ----------------
// row n = c*400 + b*100 + v  (all 400 same-class rows contiguous)
__global__ void k_gather(const float* __restrict__ feats){
    int gw   = (blockIdx.x*blockDim.x + threadIdx.x) >> 5;
    int lane = threadIdx.x & 31;
    if (gw >= NPAD) return;
    if (gw >= NROW){   // zero the pad rows every call (deterministic)
        #pragma unroll
        for (int q = 0; q < 8; q++) g_cfb[(size_t)gw*DD + lane + 32*q] = __float2bfloat16(0.0f);
        return;
    }
    int a = gw / VV, v = gw % VV;
    int b = a / CC, c = a % CC;
    int p = g_idx[gw];
    const float* fb = feats + (size_t)b*DD*HWP + p;
    float vals[8]; float ss = 0.f;
    #pragma unroll
    for (int q = 0; q < 8; q++){
        vals[q] = fb[(size_t)(lane + 32*q)*HWP];
        ss += vals[q]*vals[q];
    }
    #pragma unroll
    for (int m = 16; m > 0; m >>= 1) ss += __shfl_xor_sync(0xffffffffu, ss, m);
    float sc = 1.0f / fmaxf(sqrtf(ss), 1e-12f);
    int n = c*400 + b*100 + v;
    #pragma unroll
    for (int q = 0; q < 8; q++) g_cfb[(size_t)n*DD + lane + 32*q] = __float2bfloat16(vals[q]*sc);
}

// ---------------- kernel 4: symmetric HMMA Gram, 1-sync pipeline, band epilogue ----------------
#define SMEM_GEMM 65536
#define STG 32768       // stage stride
#define BOFF 16384      // B tile offset within stage

__global__ __launch_bounds__(256, 2) void k_gemm(){
    extern __shared__ char sm[];
    int t = threadIdx.x;
    int lane = t & 31, wid = t >> 5;

    // decode upper-triangle block index -> (bi, bj), bi <= bj
    int m = blockIdx.x;
    int bi = (int)((133.0 - sqrt(17689.0 - 8.0*(double)m)) * 0.5);
    while ((bi+1)*(133-(bi+1))/2 <= m) bi++;
    while (bi*(133-bi)/2 > m) bi--;
    int bj = bi + (m - bi*(133-bi)/2);
    int i0 = bi*128, j0 = bj*128;
    bool offdiag = (bi != bj);

    // does any class band of this row-block intersect this col-block?
    int ca0 = i0/400, ca1 = (i0+127)/400;
    bool has_pos = ((j0 < ca0*400+400) && (j0+128 > ca0*400)) ||
                   ((j0 < ca1*400+400) && (j0+128 > ca1*400));

    uint32_t sbase = smem_u32(sm);
    const char* ag = (const char*)(g_cfb + (size_t)i0*DD);
    const char* bg = (const char*)(g_cfb + (size_t)j0*DD);

    auto prefetch = [&](int kc, int st){
        uint32_t sb = sbase + st*STG;
        size_t  koff = (size_t)kc*128;
        #pragma unroll
        for (int u = 0; u < 4; u++){
            int idx = t + u*256;
            int r = idx >> 3, c = idx & 7;
            uint32_t so = (uint32_t)(r*128 + (((c ^ r) & 7))*16);
            size_t   go = (size_t)r*512 + koff + (size_t)c*16;
            cpasync16(sb + so,         ag + go);
            cpasync16(sb + BOFF + so,  bg + go);
        }
        asm volatile("cp.async.commit_group;" ::: "memory");
    };

    prefetch(0, 0);

    int wm = wid & 3, wn = wid >> 2;

    int ra = wm*32 + (lane & 7) + ((lane >> 3) & 1) * 8;
    int ca = lane >> 4;
    int rb = wn*64 + (lane & 7) + (lane >> 4) * 8;
    int cb = (lane >> 3) & 1;

    float acc[2][8][4];
    #pragma unroll
    for (int mi = 0; mi < 2; mi++)
        #pragma unroll
        for (int nj = 0; nj < 8; nj++)
            #pragma unroll
            for (int q = 0; q < 4; q++) acc[mi][nj][q] = 0.f;

    #pragma unroll
    for (int kc = 0; kc < 4; kc++){
        int st = kc & 1;
        asm volatile("cp.async.wait_group 0;" ::: "memory");
        __syncthreads();                    // all warps done with buffer st^1
        if (kc < 3) prefetch(kc+1, st^1);   // overlaps with this chunk's MMA
        uint32_t sb = sbase + st*STG;
        #pragma unroll
        for (int ks = 0; ks < 4; ks++){
            int c0 = ks*2;
            uint32_t a[2][4];
            #pragma unroll
            for (int mi = 0; mi < 2; mi++){
                int r = ra + mi*16;
                int c = c0 + ca;
                uint32_t addr = sb + (uint32_t)(r*128 + (((c ^ r) & 7))*16);
                ldsm4(a[mi], addr);
            }
            #pragma unroll
            for (int nb = 0; nb < 4; nb++){
                int r = rb + nb*16;
                int c = c0 + cb;
                uint32_t addr = sb + BOFF + (uint32_t)(r*128 + (((c ^ r) & 7))*16);
                uint32_t b[4];
                ldsm4(b, addr);
                mma16816(acc[0][2*nb],   a[0], b[0], b[1]);
                mma16816(acc[0][2*nb+1], a[0], b[2], b[3]);
                mma16816(acc[1][2*nb],   a[1], b[0], b[1]);
                mma16816(acc[1][2*nb+1], a[1], b[2], b[3]);
            }
        }
    }

    // ---- epilogue ----
    // element (mi, nj, q): row = i0 + wm*32 + mi*16 + (q>>1)*8 + lane/4
    //                      col = j0 + wn*64 + nj*8 + (lane&3)*2 + (q&1)
    const float EC = 14.42695040888963f;   // 10 * log2(e)
    int r00 = i0 + wm*32 + (lane >> 2);
    int irow[2][2]; int ilo[2][2]; bool iok[2][2];
    #pragma unroll
    for (int mi = 0; mi < 2; mi++)
        #pragma unroll
        for (int h = 0; h < 2; h++){
            irow[mi][h] = r00 + mi*16 + h*8;
            iok[mi][h]  = irow[mi][h] < NROW;
            ilo[mi][h]  = (irow[mi][h] / 400) * 400;   // class band start
        }
    float rs[2][2] = {{0.f,0.f},{0.f,0.f}};
    float rsc[16];
    #pragma unroll
    for (int q = 0; q < 16; q++) rsc[q] = 0.f;

    int jc_base = j0 + wn*64 + (lane & 3)*2;

    if (!has_pos){
        // fast path: every element is a negative (or pad, fixed by -48 later)
        #pragma unroll
        for (int nj = 0; nj < 8; nj++){
            #pragma unroll
            for (int mi = 0; mi < 2; mi++){
                #pragma unroll
                for (int h = 0; h < 2; h++){
                    float e0 = fex2(acc[mi][nj][h*2+0] * EC);
                    float e1 = fex2(acc[mi][nj][h*2+1] * EC);
                    rs[mi][h] += e0 + e1;
                    rsc[nj*2+0] += e0;
                    rsc[nj*2+1] += e1;
                }
            }
        }
    } else {
        #pragma unroll
        for (int nj = 0; nj < 8; nj++){
            int jc = jc_base + nj*8;
            #pragma unroll
            for (int mi = 0; mi < 2; mi++){
                #pragma unroll
                for (int h = 0; h < 2; h++){
                    int i  = irow[mi][h];
                    int lo = ilo[mi][h];
                    #pragma unroll
                    for (int p = 0; p < 2; p++){
                        float a = acc[mi][nj][h*2+p];
                        int j = jc + p;
                        if ((unsigned)(j - lo) < 400u){
                            if (iok[mi][h]){
                                float l = a * 10.0f;
                                g_P[(size_t)i*POS + (j - lo)] = l;
                                if (offdiag) g_P[(size_t)j*POS + (i - lo)] = l;
                            }
                        } else {
                            float e = fex2(a * EC);
                            rs[mi][h] += e;
                            rsc[nj*2+p] += e;
                        }
                    }
                }
            }
        }
    }

    // direct side: reduce across 4 lanes sharing each row (strides 1,2)
    #pragma unroll
    for (int ms = 1; ms <= 2; ms <<= 1)
        #pragma unroll
        for (int mi = 0; mi < 2; mi++)
            #pragma unroll
            for (int h = 0; h < 2; h++)
                rs[mi][h] += __shfl_xor_sync(0xffffffffu, rs[mi][h], ms);
    if ((lane & 3) == 0){
        #pragma unroll
        for (int mi = 0; mi < 2; mi++)
            #pragma unroll
            for (int h = 0; h < 2; h++)
                if (iok[mi][h]){
                    g_NSpart[(size_t)irow[mi][h]*NSW + bj*4 + wn]     = rs[mi][h];
                    g_NSpart[(size_t)irow[mi][h]*NSW + bj*4 + 2 + wn] = 0.f;
                }
    }

    // transposed side: reduce columns across the 8 row-groups (strides 4,8,16)
    if (offdiag){
        #pragma unroll
        for (int ms = 4; ms <= 16; ms <<= 1)
            #pragma unroll
            for (int q = 0; q < 16; q++)
                rsc[q] += __shfl_xor_sync(0xffffffffu, rsc[q], ms);
        if ((lane >> 2) == 0){
            #pragma unroll
            for (int nj = 0; nj < 8; nj++){
                #pragma unroll
                for (int p = 0; p < 2; p++){
                    int j = jc_base + nj*8 + p;
                    if (j < NROW) g_NSpart[(size_t)j*NSW + bi*4 + wm] = rsc[nj*2+p];
                }
            }
        }
    }
}

// ---------------- kernel 5: per-row finalize + fused deterministic final reduction ----------------
__global__ void k_finalize(float* __restrict__ out){
    __shared__ float sh[256];
    __shared__ int s_last;
    int gw   = (blockIdx.x*blockDim.x + threadIdx.x) >> 5;
    int lane = threadIdx.x & 31;

    float ns = 0.f;
    for (int jb = lane; jb < NSW; jb += 32) ns += g_NSpart[(size_t)gw*NSW + jb];
    #pragma unroll
    for (int m = 16; m > 0; m >>= 1) ns += __shfl_xor_sync(0xffffffffu, ns, m);
    ns -= NPADCOL;                 // remove exact exp(0)=1 pad-column contributions
    int kself = gw - (gw/400)*400; // self column index within class band
    float acc = 0.f;
    for (int k = lane; k < POS; k += 32){
        if (k == kself) continue;
        float l = g_P[(size_t)gw*POS + k];
        acc += l - __logf(__expf(l) + ns);
    }
    #pragma unroll
    for (int m = 16; m > 0; m >>= 1) acc += __shfl_xor_sync(0xffffffffu, acc, m);
    if (lane == 0) g_rowval[gw] = acc / 399.0f;

    // last-block fused reduction
    __threadfence();
    __syncthreads();
    if (threadIdx.x == 0) s_last = (atomicAdd(&g_cnt, 1) == (int)gridDim.x - 1);
    __syncthreads();
    if (s_last){
        __threadfence();
        int t = threadIdx.x;
        float s = 0.f;
        for (int i = t; i < NROW; i += 256) s += g_rowval[i];
        sh[t] = s; __syncthreads();
        for (int mm = 128; mm > 0; mm >>= 1){
            if (t < mm) sh[t] += sh[t+mm];
            __syncthreads();
        }
        if (t == 0){ out[0] = -(sh[0] / (float)NROW); g_cnt = 0; }
    }
}

// ---------------- launch ----------------
extern "C" void kernel_launch(void* const* d_in, const int* in_sizes, int n_in,
                              void* d_out, int out_size){
    const float* feats   = nullptr;
    const float* predict = nullptr;
    const int*   labels  = nullptr;
    for (int i = 0; i < n_in; i++){
        if      (in_sizes[i] == BB*DD*HWP)   feats   = (const float*)d_in[i];
        else if (in_sizes[i] == BB*CC*4096)  predict = (const float*)d_in[i];
        else if (in_sizes[i] == BB*HWP)      labels  = (const int*)d_in[i];
    }
    cudaFuncSetAttribute(k_gemm, cudaFuncAttributeMaxDynamicSharedMemorySize, SMEM_GEMM);
    k_pred<<<(BB*HWP)/256, 256>>>(predict);
    k_select<<<AA, 256>>>(labels);
    k_gather<<<NPAD/8, 256>>>(feats);
    k_gemm<<<NTRI, 256, SMEM_GEMM>>>();
    k_finalize<<<NROW/8, 256>>>((float*)d_out);
}

// round 16
// speedup vs baseline: 6.5145x; 1.0249x over previous
#include <cuda_runtime.h>
#include <cuda_bf16.h>
#include <cstdint>
#include <math.h>

// ---------------- problem constants ----------------
#define BB 4
#define CC 21
#define HWP 16384      // 128*128
#define DD 256
#define AA 84          // B*C anchor rows
#define VV 100         // views per anchor
#define NROW 8400      // A*V
#define NPAD 8448      // padded to 66*128
#define POS 400        // positives per row (incl. self)
#define NCB 66         // column blocks of 128
#define NSW (NCB*4)    // neg-sum partial slots per row
#define NTRI 2211      // 66*67/2 upper-triangle blocks
#define NPADCOL 48.0f  // pad columns contribute exp(0)=1 each to every row sum

// ---------------- device scratch (static, no allocs) ----------------
__device__ int   g_pred[BB*HWP];
__device__ int   g_idx[AA*VV];
__device__ __align__(16) __nv_bfloat16 g_cfb[(size_t)NPAD*DD];  // class-major normalized bf16 features
__device__ __align__(16) float g_P[(size_t)NROW*POS];        // positive logits (row-class band)
__device__ __align__(16) float g_NSpart[(size_t)NROW*NSW];   // per (row, block-group, sub) exp-sum partials
__device__ float g_rowval[NROW];
__device__ int   g_cnt;                        // last-block counter (reset by last block)

// ---------------- helpers ----------------
__device__ __forceinline__ uint32_t smem_u32(const void* p){
    uint32_t a;
    asm("{ .reg .u64 t; cvta.to.shared.u64 t, %1; cvt.u32.u64 %0, t; }" : "=r"(a) : "l"(p));
    return a;
}
__device__ __forceinline__ void ldsm4(uint32_t* r, uint32_t addr){
    asm volatile("ldmatrix.sync.aligned.m8n8.x4.shared.b16 {%0,%1,%2,%3}, [%4];"
        : "=r"(r[0]), "=r"(r[1]), "=r"(r[2]), "=r"(r[3]) : "r"(addr));
}
__device__ __forceinline__ void mma16816(float* d, const uint32_t* a, uint32_t b0, uint32_t b1){
    asm volatile("mma.sync.aligned.m16n8k16.row.col.f32.bf16.bf16.f32 "
        "{%0,%1,%2,%3}, {%4,%5,%6,%7}, {%8,%9}, {%0,%1,%2,%3};"
        : "+f"(d[0]), "+f"(d[1]), "+f"(d[2]), "+f"(d[3])
        : "r"(a[0]), "r"(a[1]), "r"(a[2]), "r"(a[3]), "r"(b0), "r"(b1));
}
__device__ __forceinline__ void cpasync16(uint32_t saddr, const void* gaddr){
    asm volatile("cp.async.cg.shared.global [%0], [%1], 16;" :: "r"(saddr), "l"(gaddr));
}
__device__ __forceinline__ float fex2(float x){
    float r;
    asm("ex2.approx.f32 %0, %1;" : "=f"(r) : "f"(x));
    return r;
}

// ---------------- kernel 1: bilinear upsample (64->128) + argmax over 21 classes ----------------
__global__ void k_pred(const float* __restrict__ predict){
    int tid = blockIdx.x*blockDim.x + threadIdx.x;
    if (tid >= BB*HWP) return;
    int b = tid >> 14;
    int p = tid & (HWP-1);
    int y = p >> 7, x = p & 127;
    float fy = fminf(fmaxf(0.5f*(float)y - 0.25f, 0.0f), 63.0f);
    float fx = fminf(fmaxf(0.5f*(float)x - 0.25f, 0.0f), 63.0f);
    int y0 = (int)fy, x0 = (int)fx;
    float wy = fy - (float)y0, wx = fx - (float)x0;
    int y1 = min(y0+1, 63), x1 = min(x0+1, 63);
    const float* pb = predict + (size_t)b*CC*4096;
    float best = -3.4e38f; int bc = 0;
    #pragma unroll
    for (int c = 0; c < CC; c++){
        const float* pc = pb + c*4096;
        float v00 = pc[y0*64+x0], v01 = pc[y0*64+x1];
        float v10 = pc[y1*64+x0], v11 = pc[y1*64+x1];
        float top = v00 + wx*(v01-v00);
        float bot = v10 + wx*(v11-v10);
        float v = top + wy*(bot-top);
        if (v > best){ best = v; bc = c; }
    }
    g_pred[tid] = bc;
}

// ---------------- kernel 2: per-(b,c) hard/easy selection (deterministic rank-based) ----------------
__global__ void k_select(const int* __restrict__ labels){
    __shared__ int sh_h[256], sh_e[256], sh_ph[256], sh_pe[256];
    __shared__ int s_hk, s_ek, s_S;
    int row = blockIdx.x;
    int b = row / CC, c = row % CC;
    int t = threadIdx.x;
    unsigned long long hbits = 0ull, ebits = 0ull;
    int base = b*HWP + t*64;
    for (int q = 0; q < 64; q++){
        int pr = g_pred[base+q];
        int lb = labels[base+q];
        if (pr == c){ if (lb == c) ebits |= (1ull<<q); else hbits |= (1ull<<q); }
    }
    sh_h[t] = __popcll(hbits); sh_e[t] = __popcll(ebits);
    __syncthreads();
    if (t == 0){
        int rh = 0, re = 0;
        for (int u = 0; u < 256; u++){ sh_ph[u]=rh; sh_pe[u]=re; rh+=sh_h[u]; re+=sh_e[u]; }
        int nh = rh, ne = re;
        int hk;
        if (nh >= 50 && ne >= 50) hk = 50;
        else if (nh >= 50)        hk = 100 - ne;
        else                      hk = nh;
        int ek = 100 - hk;
        s_hk = hk; s_ek = ek;
        s_S = min(nh, hk) + min(ne, ek);
    }
    __syncthreads();
    int hb = sh_ph[t], eb = sh_pe[t];
    int hk = s_hk, ek = s_ek, S = s_S;
    for (int q = 0; q < 64; q++){
        int p = t*64 + q;
        int slot;
        if ((hbits>>q)&1ull){
            if (hb < hk) slot = hb + min(eb, ek);
            else         slot = S + (p - min(hb,hk) - min(eb,ek));
            hb++;
        } else if ((ebits>>q)&1ull){
            if (eb < ek) slot = min(hb, hk) + eb;
            else         slot = S + (p - min(hb,hk) - min(eb,ek));
            eb++;
        } else {
            slot = S + (p - min(hb,hk) - min(eb,ek));
        }
        if (slot < VV) g_idx[row*VV + slot] = p;
    }
}

// ---------------- kernel 3: gather + L2-normalize -> bf16, CLASS-MAJOR rows ----------------
// row n = c*400 + b*100 + v  (all 400 same-class rows contiguous)
__global__ void k_gather(const float* __restrict__ feats){
    int gw   = (blockIdx.x*blockDim.x + threadIdx.x) >> 5;
    int lane = threadIdx.x & 31;
    if (gw >= NPAD) return;
    if (gw >= NROW){   // zero the pad rows every call (deterministic)
        #pragma unroll
        for (int q = 0; q < 8; q++) g_cfb[(size_t)gw*DD + lane + 32*q] = __float2bfloat16(0.0f);
        return;
    }
    int a = gw / VV, v = gw % VV;
    int b = a / CC, c = a % CC;
    int p = g_idx[gw];
    const float* fb = feats + (size_t)b*DD*HWP + p;
    float vals[8]; float ss = 0.f;
    #pragma unroll
    for (int q = 0; q < 8; q++){
        vals[q] = fb[(size_t)(lane + 32*q)*HWP];
        ss += vals[q]*vals[q];
    }
    #pragma unroll
    for (int m = 16; m > 0; m >>= 1) ss += __shfl_xor_sync(0xffffffffu, ss, m);
    float sc = 1.0f / fmaxf(sqrtf(ss), 1e-12f);
    int n = c*400 + b*100 + v;
    #pragma unroll
    for (int q = 0; q < 8; q++) g_cfb[(size_t)n*DD + lane + 32*q] = __float2bfloat16(vals[q]*sc);
}

// ---------------- kernel 4: symmetric HMMA Gram, 3-stage pipeline, band epilogue ----------------
#define SMEM_GEMM (3*32768)
#define STG 32768       // stage stride
#define BOFF 16384      // B tile offset within stage

__global__ __launch_bounds__(256, 2) void k_gemm(){
    extern __shared__ char sm[];
    int t = threadIdx.x;
    int lane = t & 31, wid = t >> 5;

    // decode upper-triangle block index -> (bi, bj), bi <= bj
    int m = blockIdx.x;
    int bi = (int)((133.0 - sqrt(17689.0 - 8.0*(double)m)) * 0.5);
    while ((bi+1)*(133-(bi+1))/2 <= m) bi++;
    while (bi*(133-bi)/2 > m) bi--;
    int bj = bi + (m - bi*(133-bi)/2);
    int i0 = bi*128, j0 = bj*128;
    bool offdiag = (bi != bj);

    // does any class band of this row-block intersect this col-block?
    int ca0 = i0/400, ca1 = (i0+127)/400;
    bool has_pos = ((j0 < ca0*400+400) && (j0+128 > ca0*400)) ||
                   ((j0 < ca1*400+400) && (j0+128 > ca1*400));

    uint32_t sbase = smem_u32(sm);
    const char* ag = (const char*)(g_cfb + (size_t)i0*DD);
    const char* bg = (const char*)(g_cfb + (size_t)j0*DD);

    auto prefetch = [&](int kc, int st){
        uint32_t sb = sbase + st*STG;
        size_t  koff = (size_t)kc*128;
        #pragma unroll
        for (int u = 0; u < 4; u++){
            int idx = t + u*256;
            int r = idx >> 3, c = idx & 7;
            uint32_t so = (uint32_t)(r*128 + (((c ^ r) & 7))*16);
            size_t   go = (size_t)r*512 + koff + (size_t)c*16;
            cpasync16(sb + so,         ag + go);
            cpasync16(sb + BOFF + so,  bg + go);
        }
        asm volatile("cp.async.commit_group;" ::: "memory");
    };

    // two chunks in flight from the start
    prefetch(0, 0);
    prefetch(1, 1);

    int wm = wid & 3, wn = wid >> 2;

    int ra = wm*32 + (lane & 7) + ((lane >> 3) & 1) * 8;
    int ca = lane >> 4;
    int rb = wn*64 + (lane & 7) + (lane >> 4) * 8;
    int cb = (lane >> 3) & 1;

    float acc[2][8][4];
    #pragma unroll
    for (int mi = 0; mi < 2; mi++)
        #pragma unroll
        for (int nj = 0; nj < 8; nj++)
            #pragma unroll
            for (int q = 0; q < 4; q++) acc[mi][nj][q] = 0.f;

    #pragma unroll
    for (int kc = 0; kc < 4; kc++){
        int st = kc % 3;
        if (kc < 3) asm volatile("cp.async.wait_group 1;" ::: "memory");
        else        asm volatile("cp.async.wait_group 0;" ::: "memory");
        __syncthreads();                    // all warps done with the stage being refilled
        if (kc < 2) prefetch(kc+2, (kc+2) % 3);   // overlaps with this chunk's MMA
        uint32_t sb = sbase + st*STG;
        #pragma unroll
        for (int ks = 0; ks < 4; ks++){
            int c0 = ks*2;
            uint32_t a[2][4];
            #pragma unroll
            for (int mi = 0; mi < 2; mi++){
                int r = ra + mi*16;
                int c = c0 + ca;
                uint32_t addr = sb + (uint32_t)(r*128 + (((c ^ r) & 7))*16);
                ldsm4(a[mi], addr);
            }
            #pragma unroll
            for (int nb = 0; nb < 4; nb++){
                int r = rb + nb*16;
                int c = c0 + cb;
                uint32_t addr = sb + BOFF + (uint32_t)(r*128 + (((c ^ r) & 7))*16);
                uint32_t b[4];
                ldsm4(b, addr);
                mma16816(acc[0][2*nb],   a[0], b[0], b[1]);
                mma16816(acc[0][2*nb+1], a[0], b[2], b[3]);
                mma16816(acc[1][2*nb],   a[1], b[0], b[1]);
                mma16816(acc[1][2*nb+1], a[1], b[2], b[3]);
            }
        }
    }

    // ---- epilogue ----
    // element (mi, nj, q): row = i0 + wm*32 + mi*16 + (q>>1)*8 + lane/4
    //                      col = j0 + wn*64 + nj*8 + (lane&3)*2 + (q&1)
    const float EC = 14.42695040888963f;   // 10 * log2(e)
    int r00 = i0 + wm*32 + (lane >> 2);
    int irow[2][2]; int ilo[2][2]; bool iok[2][2];
    #pragma unroll
    for (int mi = 0; mi < 2; mi++)
        #pragma unroll
        for (int h = 0; h < 2; h++){
            irow[mi][h] = r00 + mi*16 + h*8;
            iok[mi][h]  = irow[mi][h] < NROW;
            ilo[mi][h]  = (irow[mi][h] / 400) * 400;   // class band start
        }
    float rs[2][2] = {{0.f,0.f},{0.f,0.f}};
    float rsc[16];
    #pragma unroll
    for (int q = 0; q < 16; q++) rsc[q] = 0.f;

    int jc_base = j0 + wn*64 + (lane & 3)*2;

    if (!has_pos){
        // fast path: every element is a negative (or pad, fixed by -48 later)
        #pragma unroll
        for (int nj = 0; nj < 8; nj++){
            #pragma unroll
            for (int mi = 0; mi < 2; mi++){
                #pragma unroll
                for (int h = 0; h < 2; h++){
                    float e0 = fex2(acc[mi][nj][h*2+0] * EC);
                    float e1 = fex2(acc[mi][nj][h*2+1] * EC);
                    rs[mi][h] += e0 + e1;
                    rsc[nj*2+0] += e0;
                    rsc[nj*2+1] += e1;
                }
            }
        }
    } else {
        #pragma unroll
        for (int nj = 0; nj < 8; nj++){
            int jc = jc_base + nj*8;
            #pragma unroll
            for (int mi = 0; mi < 2; mi++){
                #pragma unroll
                for (int h = 0; h < 2; h++){
                    int i  = irow[mi][h];
                    int lo = ilo[mi][h];
                    #pragma unroll
                    for (int p = 0; p < 2; p++){
                        float a = acc[mi][nj][h*2+p];
                        int j = jc + p;
                        if ((unsigned)(j - lo) < 400u){
                            if (iok[mi][h]){
                                float l = a * 10.0f;
                                g_P[(size_t)i*POS + (j - lo)] = l;
                                if (offdiag) g_P[(size_t)j*POS + (i - lo)] = l;
                            }
                        } else {
                            float e = fex2(a * EC);
                            rs[mi][h] += e;
                            rsc[nj*2+p] += e;
                        }
                    }
                }
            }
        }
    }

    // direct side: reduce across 4 lanes sharing each row (strides 1,2)
    #pragma unroll
    for (int ms = 1; ms <= 2; ms <<= 1)
        #pragma unroll
        for (int mi = 0; mi < 2; mi++)
            #pragma unroll
            for (int h = 0; h < 2; h++)
                rs[mi][h] += __shfl_xor_sync(0xffffffffu, rs[mi][h], ms);
    if ((lane & 3) == 0){
        #pragma unroll
        for (int mi = 0; mi < 2; mi++)
            #pragma unroll
            for (int h = 0; h < 2; h++)
                if (iok[mi][h]){
                    g_NSpart[(size_t)irow[mi][h]*NSW + bj*4 + wn]     = rs[mi][h];
                    g_NSpart[(size_t)irow[mi][h]*NSW + bj*4 + 2 + wn] = 0.f;
                }
    }

    // transposed side: reduce columns across the 8 row-groups (strides 4,8,16)
    if (offdiag){
        #pragma unroll
        for (int ms = 4; ms <= 16; ms <<= 1)
            #pragma unroll
            for (int q = 0; q < 16; q++)
                rsc[q] += __shfl_xor_sync(0xffffffffu, rsc[q], ms);
        if ((lane >> 2) == 0){
            #pragma unroll
            for (int nj = 0; nj < 8; nj++){
                #pragma unroll
                for (int p = 0; p < 2; p++){
                    int j = jc_base + nj*8 + p;
                    if (j < NROW) g_NSpart[(size_t)j*NSW + bi*4 + wm] = rsc[nj*2+p];
                }
            }
        }
    }
}

// ---------------- kernel 5: per-row finalize + fused deterministic final reduction ----------------
__global__ void k_finalize(float* __restrict__ out){
    __shared__ float sh[256];
    __shared__ int s_last;
    int gw   = (blockIdx.x*blockDim.x + threadIdx.x) >> 5;
    int lane = threadIdx.x & 31;

    // neg-sum partials: 264 floats = 66 float4 per row
    float ns = 0.f;
    const float4* np = (const float4*)&g_NSpart[(size_t)gw*NSW];
    for (int j4 = lane; j4 < NSW/4; j4 += 32){
        float4 v = np[j4];
        ns += (v.x + v.y) + (v.z + v.w);
    }
    #pragma unroll
    for (int m = 16; m > 0; m >>= 1) ns += __shfl_xor_sync(0xffffffffu, ns, m);
    ns -= NPADCOL;                 // remove exact exp(0)=1 pad-column contributions
    int kself = gw - (gw/400)*400; // self column index within class band
    float acc = 0.f;
    const float4* pp = (const float4*)&g_P[(size_t)gw*POS];
    for (int k4 = lane; k4 < POS/4; k4 += 32){
        float4 v = pp[k4];
        float l[4] = {v.x, v.y, v.z, v.w};
        #pragma unroll
        for (int e = 0; e < 4; e++){
            int k = k4*4 + e;
            if (k == kself) continue;
            acc += l[e] - __logf(__expf(l[e]) + ns);
        }
    }
    #pragma unroll
    for (int m = 16; m > 0; m >>= 1) acc += __shfl_xor_sync(0xffffffffu, acc, m);
    if (lane == 0) g_rowval[gw] = acc / 399.0f;

    // last-block fused reduction
    __threadfence();
    __syncthreads();
    if (threadIdx.x == 0) s_last = (atomicAdd(&g_cnt, 1) == (int)gridDim.x - 1);
    __syncthreads();
    if (s_last){
        __threadfence();
        int t = threadIdx.x;
        float s = 0.f;
        for (int i = t; i < NROW; i += 256) s += g_rowval[i];
        sh[t] = s; __syncthreads();
        for (int mm = 128; mm > 0; mm >>= 1){
            if (t < mm) sh[t] += sh[t+mm];
            __syncthreads();
        }
        if (t == 0){ out[0] = -(sh[0] / (float)NROW); g_cnt = 0; }
    }
}

// ---------------- launch ----------------
extern "C" void kernel_launch(void* const* d_in, const int* in_sizes, int n_in,
                              void* d_out, int out_size){
    const float* feats   = nullptr;
    const float* predict = nullptr;
    const int*   labels  = nullptr;
    for (int i = 0; i < n_in; i++){
        if      (in_sizes[i] == BB*DD*HWP)   feats   = (const float*)d_in[i];
        else if (in_sizes[i] == BB*CC*4096)  predict = (const float*)d_in[i];
        else if (in_sizes[i] == BB*HWP)      labels  = (const int*)d_in[i];
    }
    cudaFuncSetAttribute(k_gemm, cudaFuncAttributeMaxDynamicSharedMemorySize, SMEM_GEMM);
    k_pred<<<(BB*HWP)/256, 256>>>(predict);
    k_select<<<AA, 256>>>(labels);
    k_gather<<<NPAD/8, 256>>>(feats);
    k_gemm<<<NTRI, 256, SMEM_GEMM>>>();
    k_finalize<<<NROW/8, 256>>>((float*)d_out);
}